// round 1
// baseline (speedup 1.0000x reference)
#include <cuda_runtime.h>
#include <math.h>

// Problem constants (fixed shapes for this problem)
constexpr int Bv = 2048;   // queries
constexpr int Nv = 50000;  // embeddings
constexpr int Cv = 768;    // channels
constexpr int Kv = 16;     // top-k
constexpr int TOPC = 64;       // candidate margin (>> k; robust to later low-precision GEMM)
constexpr int CAND_MAX = 256;  // hard cap on collected candidates

// Scratch (static __device__ — no allocations allowed)
__device__ float g_sims[(size_t)Bv * Nv];     // ~410 MB approx cosine sims
__device__ float g_enorm[Nv];
__device__ float g_xnorm[Bv];
__device__ int   g_cand[Bv * CAND_MAX];
__device__ int   g_ccnt[Bv];
__device__ int   g_topidx[Bv * Kv];

// ---------------------------------------------------------------------------
// Pass 0: row norms of E (first Nv warps) and X (next Bv warps). One warp/row.
// ---------------------------------------------------------------------------
__global__ void norms_kernel(const float* __restrict__ E, const float* __restrict__ X) {
    int gw   = (blockIdx.x * blockDim.x + threadIdx.x) >> 5;
    int lane = threadIdx.x & 31;
    const float* src;
    float* dst;
    if (gw < Nv)            { src = E + (size_t)gw * Cv;        dst = &g_enorm[gw]; }
    else if (gw < Nv + Bv)  { src = X + (size_t)(gw - Nv) * Cv; dst = &g_xnorm[gw - Nv]; }
    else return;

    const float4* r = (const float4*)src;
    float s = 0.f;
#pragma unroll
    for (int t = 0; t < Cv / 128; t++) {
        float4 v = r[lane + t * 32];
        s = fmaf(v.x, v.x, s); s = fmaf(v.y, v.y, s);
        s = fmaf(v.z, v.z, s); s = fmaf(v.w, v.w, s);
    }
#pragma unroll
    for (int o = 16; o; o >>= 1) s += __shfl_down_sync(0xffffffffu, s, o);
    if (lane == 0) *dst = sqrtf(s);
}

// ---------------------------------------------------------------------------
// Pass 1: approx cosine sims. Tiled fp32 GEMM: sims[b][n] = (x_b . e_n)/(|x_b||e_n|)
// 64x64 block tile, BK=16, 256 threads, 4x4 per-thread micro-tile.
// ---------------------------------------------------------------------------
__global__ __launch_bounds__(256) void gemm_sims_kernel(const float* __restrict__ X,
                                                        const float* __restrict__ E) {
    __shared__ float Xs[16][64];
    __shared__ float Es[16][64];

    int tid = threadIdx.x;
    int n0 = blockIdx.x * 64;
    int m0 = blockIdx.y * 64;

    int lr = tid >> 2;          // 0..63  (row within tile for loads)
    int lc = (tid & 3) << 2;    // 0,4,8,12 (col4 within k-tile)
    int tx = tid & 15;          // output col group
    int ty = tid >> 4;          // output row group

    float acc[4][4] = {};

    const float* xg = X + (size_t)(m0 + lr) * Cv + lc;
    int er = n0 + lr;
    bool evalid = (er < Nv);
    const float* eg = E + (size_t)(evalid ? er : 0) * Cv + lc;

    for (int k0 = 0; k0 < Cv; k0 += 16) {
        float4 xv = *(const float4*)(xg + k0);
        float4 ev = make_float4(0.f, 0.f, 0.f, 0.f);
        if (evalid) ev = *(const float4*)(eg + k0);

        __syncthreads();
        Xs[lc + 0][lr] = xv.x; Xs[lc + 1][lr] = xv.y;
        Xs[lc + 2][lr] = xv.z; Xs[lc + 3][lr] = xv.w;
        Es[lc + 0][lr] = ev.x; Es[lc + 1][lr] = ev.y;
        Es[lc + 2][lr] = ev.z; Es[lc + 3][lr] = ev.w;
        __syncthreads();

#pragma unroll
        for (int kk = 0; kk < 16; kk++) {
            float4 a = *(const float4*)&Xs[kk][ty << 2];
            float4 bb = *(const float4*)&Es[kk][tx << 2];
            float av[4] = {a.x, a.y, a.z, a.w};
            float bv[4] = {bb.x, bb.y, bb.z, bb.w};
#pragma unroll
            for (int i = 0; i < 4; i++)
#pragma unroll
                for (int j = 0; j < 4; j++)
                    acc[i][j] = fmaf(av[i], bv[j], acc[i][j]);
        }
    }

    float rx[4], re[4];
#pragma unroll
    for (int i = 0; i < 4; i++) rx[i] = 1.f / g_xnorm[m0 + (ty << 2) + i];
#pragma unroll
    for (int j = 0; j < 4; j++) {
        int n = n0 + (tx << 2) + j;
        re[j] = (n < Nv) ? (1.f / g_enorm[n]) : 0.f;
    }
#pragma unroll
    for (int i = 0; i < 4; i++) {
        size_t rowoff = (size_t)(m0 + (ty << 2) + i) * Nv;
#pragma unroll
        for (int j = 0; j < 4; j++) {
            int n = n0 + (tx << 2) + j;
            if (n < Nv) g_sims[rowoff + n] = acc[i][j] * rx[i] * re[j];
        }
    }
}

// ---------------------------------------------------------------------------
// Pass 2: per-row candidate selection: top-TOPC by approx sim via 16-bit radix
// threshold (2 histogram passes + 1 collect pass). One CTA per row.
// ---------------------------------------------------------------------------
__device__ __forceinline__ unsigned fkey(float f) {
    unsigned u = __float_as_uint(f);
    return (u & 0x80000000u) ? ~u : (u | 0x80000000u);  // order-preserving map
}

__global__ __launch_bounds__(256) void select_cand_kernel() {
    int b = blockIdx.x;
    int tid = threadIdx.x;
    const float* row = g_sims + (size_t)b * Nv;

    __shared__ unsigned hist[256];
    __shared__ int s_b1, s_above1;
    __shared__ unsigned s_thr;
    __shared__ int s_cnt;

    // --- histogram of top 8 bits ---
    hist[tid] = 0;
    __syncthreads();
    for (int i = tid; i < Nv; i += 256)
        atomicAdd(&hist[fkey(row[i]) >> 24], 1u);
    __syncthreads();
    if (tid == 0) {
        int run = 0;
        for (int v = 255; v >= 0; v--) {
            run += (int)hist[v];
            if (run >= TOPC) { s_b1 = v; s_above1 = run - (int)hist[v]; break; }
        }
    }
    __syncthreads();
    int b1 = s_b1, above1 = s_above1;

    // --- histogram of next 8 bits within bin b1 ---
    hist[tid] = 0;
    __syncthreads();
    for (int i = tid; i < Nv; i += 256) {
        unsigned u = fkey(row[i]);
        if ((int)(u >> 24) == b1) atomicAdd(&hist[(u >> 16) & 255u], 1u);
    }
    __syncthreads();
    if (tid == 0) {
        int run = above1;
        s_thr = (unsigned)b1 << 24;  // fallback (whole bin)
        for (int v = 255; v >= 0; v--) {
            run += (int)hist[v];
            if (run >= TOPC) { s_thr = ((unsigned)b1 << 24) | ((unsigned)v << 16); break; }
        }
        s_cnt = 0;
    }
    __syncthreads();
    unsigned thr = s_thr;

    // --- collect candidates with key >= thr ---
    for (int i = tid; i < Nv; i += 256) {
        if (fkey(row[i]) >= thr) {
            int p = atomicAdd(&s_cnt, 1);
            if (p < CAND_MAX) g_cand[b * CAND_MAX + p] = i;
        }
    }
    __syncthreads();
    if (tid == 0) g_ccnt[b] = (s_cnt < CAND_MAX) ? s_cnt : CAND_MAX;
}

// ---------------------------------------------------------------------------
// Pass 3: exact (double-precision) rescore of candidates + exact top-16.
// One CTA (256 thr / 8 warps) per row. One warp per candidate dot product.
// ---------------------------------------------------------------------------
__global__ __launch_bounds__(256) void rescore_topk_kernel(const float* __restrict__ X,
                                                           const float* __restrict__ E) {
    int b = blockIdx.x;
    int tid = threadIdx.x;
    int warp = tid >> 5, lane = tid & 31;

    __shared__ float xs[Cv];
    __shared__ double s_sc[CAND_MAX];
    __shared__ int s_id[CAND_MAX];
    __shared__ double wsum[8];
    __shared__ double s_xn2;
    __shared__ double rv[256];
    __shared__ int rslot[256];

    // load x row + double ||x||^2
    double p = 0.0;
    for (int c = tid; c < Cv; c += 256) {
        float v = X[(size_t)b * Cv + c];
        xs[c] = v;
        p += (double)v * (double)v;
    }
#pragma unroll
    for (int o = 16; o; o >>= 1) p += __shfl_down_sync(0xffffffffu, p, o);
    if (lane == 0) wsum[warp] = p;
    __syncthreads();
    if (tid == 0) {
        double t = 0.0;
        for (int i = 0; i < 8; i++) t += wsum[i];
        s_xn2 = t;
    }
    __syncthreads();

    int cnt = g_ccnt[b];
    for (int ci = warp; ci < cnt; ci += 8) {
        int n = g_cand[b * CAND_MAX + ci];
        const float* er = E + (size_t)n * Cv;
        double d = 0.0, e2 = 0.0;
        for (int c = lane; c < Cv; c += 32) {
            double ev = (double)er[c];
            d = fma((double)xs[c], ev, d);
            e2 = fma(ev, ev, e2);
        }
#pragma unroll
        for (int o = 16; o; o >>= 1) {
            d += __shfl_down_sync(0xffffffffu, d, o);
            e2 += __shfl_down_sync(0xffffffffu, e2, o);
        }
        if (lane == 0) {
            double den = fmax(sqrt(s_xn2) * sqrt(e2), 1e-8);
            s_sc[ci] = d / den;
            s_id[ci] = n;
        }
    }
    // pad unused slots
    for (int ci = cnt + tid; ci < CAND_MAX; ci += 256) {
        s_sc[ci] = -1e300;
        s_id[ci] = 0x7fffffff;
    }
    __syncthreads();

    // exact top-16, descending, tie-break by smaller embedding index
    for (int r = 0; r < Kv; r++) {
        rv[tid] = s_sc[tid];
        rslot[tid] = tid;
        __syncthreads();
        for (int s = 128; s > 0; s >>= 1) {
            if (tid < s) {
                double v1 = rv[tid], v2 = rv[tid + s];
                int sl1 = rslot[tid], sl2 = rslot[tid + s];
                bool take2 = (v2 > v1) || (v2 == v1 && s_id[sl2] < s_id[sl1]);
                if (take2) { rv[tid] = v2; rslot[tid] = sl2; }
            }
            __syncthreads();
        }
        if (tid == 0) {
            int sl = rslot[0];
            g_topidx[b * Kv + r] = s_id[sl];
            s_sc[sl] = -1e300;
        }
        __syncthreads();
    }
}

// ---------------------------------------------------------------------------
// Pass 4: gather with torch's reshape/permute interleave:
//   out[b][j][:] = E[ idx[j*128 + b/16][b%16] ][:]   (B=2048, k=16)
// One CTA per output row (b,j); 192 threads x float4.
// ---------------------------------------------------------------------------
__global__ __launch_bounds__(192) void gather_kernel(const float* __restrict__ E,
                                                     float* __restrict__ out) {
    int row = blockIdx.x;          // row = b*Kv + j
    int b = row >> 4;              // /16
    int j = row & 15;
    int src = g_topidx[((j << 7) + (b >> 4)) * Kv + (b & 15)];
    const float4* e4 = (const float4*)(E + (size_t)src * Cv);
    float4* o4 = (float4*)(out + (size_t)row * Cv);
    o4[threadIdx.x] = e4[threadIdx.x];
}

// ---------------------------------------------------------------------------
extern "C" void kernel_launch(void* const* d_in, const int* in_sizes, int n_in,
                              void* d_out, int out_size) {
    const float* X = (const float*)d_in[0];  // (B, C)
    const float* E = (const float*)d_in[1];  // (N, C)
    float* out = (float*)d_out;              // (B, k, C)

    // Pass 0: norms (one warp per row, Nv + Bv rows)
    {
        int warps = Nv + Bv;
        int blocks = (warps * 32 + 255) / 256;
        norms_kernel<<<blocks, 256>>>(E, X);
    }
    // Pass 1: approx cosine sims
    {
        dim3 grid((Nv + 63) / 64, Bv / 64);
        gemm_sims_kernel<<<grid, 256>>>(X, E);
    }
    // Pass 2: candidate selection
    select_cand_kernel<<<Bv, 256>>>();
    // Pass 3: exact rescore + top-16
    rescore_topk_kernel<<<Bv, 256>>>(X, E);
    // Pass 4: gather
    gather_kernel<<<Bv * Kv, 192>>>(E, out);
}

// round 6
// speedup vs baseline: 1.8905x; 1.8905x over previous
#include <cuda_runtime.h>
#include <cuda_bf16.h>
#include <math.h>
#include <stdint.h>

// Problem constants
constexpr int Bv = 2048;   // queries
constexpr int Nv = 50000;  // embeddings
constexpr int Cv = 768;    // channels
constexpr int Kv = 16;     // top-k
constexpr int TOPC = 128;      // candidate margin (absorbs bf16 sim error)
constexpr int CAND_MAX = 320;

// GEMM tiling
constexpr int TM = 128, TN = 128, TK = 32;
constexpr int NTILES_N = (Nv + TN - 1) / TN;  // 391
constexpr int KCHUNKS = Cv / TK;              // 24

// Scratch (static __device__ — no allocations allowed).
// NOTE: these are referenced ONLY from device code. Passing a __device__
// global as a host-side kernel argument is UB (that was the round-2..5 bug).
__device__ float          g_sims[(size_t)Bv * Nv];   // ~410 MB
__device__ __nv_bfloat16  g_Xb[(size_t)Bv * Cv];
__device__ __nv_bfloat16  g_Eb[(size_t)Nv * Cv];
__device__ float          g_rinv[NTILES_N * TN];     // 1/||e_n||, padded
__device__ int            g_cand[Bv * CAND_MAX];
__device__ int            g_ccnt[Bv];
__device__ int            g_topidx[Bv * Kv];

// ---------------------------------------------------------------------------
// fp32 -> bf16 converts (write device globals by direct symbol reference)
// ---------------------------------------------------------------------------
__device__ __forceinline__ uint2 cvt4(const float4 v) {
    __nv_bfloat162 p0 = __float22bfloat162_rn(make_float2(v.x, v.y));
    __nv_bfloat162 p1 = __float22bfloat162_rn(make_float2(v.z, v.w));
    uint2 u;
    u.x = *(uint32_t*)&p0;
    u.y = *(uint32_t*)&p1;
    return u;
}

__global__ void convert_x_kernel(const float* __restrict__ src) {
    int i = blockIdx.x * blockDim.x + threadIdx.x;
    if (i >= Bv * Cv / 4) return;
    ((uint2*)g_Xb)[i] = cvt4(((const float4*)src)[i]);
}

__global__ void convert_e_kernel(const float* __restrict__ src) {
    int i = blockIdx.x * blockDim.x + threadIdx.x;
    if (i >= Nv * Cv / 4) return;
    ((uint2*)g_Eb)[i] = cvt4(((const float4*)src)[i]);
}

// ---------------------------------------------------------------------------
// E row reciprocal norms (fp32 exact). One warp per row.
// ---------------------------------------------------------------------------
__global__ void norms_kernel(const float* __restrict__ E) {
    int gw = (blockIdx.x * blockDim.x + threadIdx.x) >> 5;
    int lane = threadIdx.x & 31;
    if (gw >= Nv) return;
    const float4* r = (const float4*)(E + (size_t)gw * Cv);
    float s = 0.f;
#pragma unroll
    for (int t = 0; t < Cv / 128; t++) {
        float4 v = r[lane + t * 32];
        s = fmaf(v.x, v.x, s); s = fmaf(v.y, v.y, s);
        s = fmaf(v.z, v.z, s); s = fmaf(v.w, v.w, s);
    }
#pragma unroll
    for (int o = 16; o; o >>= 1) s += __shfl_down_sync(0xffffffffu, s, o);
    if (lane == 0) g_rinv[gw] = rsqrtf(s);
}

// ---------------------------------------------------------------------------
// Pass 1: bf16 mma.sync GEMM -> scaled sims (dot * 1/||e||).
// Conservative: single SMEM buffer, direct LDS.b32 fragment loads,
// strict sync->store->sync->compute per K chunk.
// CTA tile 128x128, 8 warps (2x4), warp tile 64x32, m16n8k16 HMMA.
// ---------------------------------------------------------------------------
__device__ __forceinline__ uint32_t smem_u32(const void* p) {
    uint32_t a;
    asm("{ .reg .u64 t; cvta.to.shared.u64 t, %1; cvt.u32.u64 %0, t; }" : "=r"(a) : "l"(p));
    return a;
}

__device__ __forceinline__ uint32_t lds32(uint32_t addr) {
    uint32_t v;
    asm volatile("ld.shared.b32 %0, [%1];" : "=r"(v) : "r"(addr));
    return v;
}

// SMEM addr of (row r, 16B-unit u) within a 128x32 bf16 chunk (64B rows).
__device__ __forceinline__ uint32_t sw_addr(uint32_t base, int r, int u) {
    return base + (uint32_t)r * 64 + (uint32_t)((u ^ ((r >> 1) & 3)) << 4);
}

__global__ __launch_bounds__(256) void mma_sims_kernel() {
    __shared__ __align__(16) char smem[2 * 8192];  // A @ 0 ; B @ 8192
    uint32_t sA = smem_u32(smem);
    uint32_t sB = sA + 8192;

    int tid = threadIdx.x;
    int lane = tid & 31, wid = tid >> 5;
    int n0 = blockIdx.x * TN;
    int m0 = blockIdx.y * TM;

    int wm = wid & 1;        // 0..1
    int wn = wid >> 1;       // 0..3
    int mbase = wm * 64;     // warp tile M offset in CTA tile
    int nbase = wn * 32;     // warp tile N offset

    int gid = lane >> 2;     // 0..7  (groupID)
    int ctid = lane & 3;     // 0..3  (threadID_in_group)
    int inoff = ctid * 4;    // byte offset within 16B unit (2 bf16 per reg)

    // Global load assignment: this thread handles (row tid>>2, unit tid&3)
    // and (row (tid>>2)+64, same unit).
    int r0l = tid >> 2, u0l = tid & 3;
    int r1l = r0l + 64;

    const __nv_bfloat16* gA = g_Xb + (size_t)m0 * Cv;
    int er0 = n0 + r0l, er1 = n0 + r1l;
    bool v0 = er0 < Nv, v1 = er1 < Nv;
    const __nv_bfloat16* gB0 = g_Eb + (size_t)(v0 ? er0 : 0) * Cv;
    const __nv_bfloat16* gB1 = g_Eb + (size_t)(v1 ? er1 : 0) * Cv;
    const __nv_bfloat16* gA0 = gA + (size_t)r0l * Cv;
    const __nv_bfloat16* gA1 = gA + (size_t)r1l * Cv;

    float acc[4][4][4];
#pragma unroll
    for (int i = 0; i < 4; i++)
#pragma unroll
        for (int j = 0; j < 4; j++)
#pragma unroll
            for (int q = 0; q < 4; q++) acc[i][j][q] = 0.f;

    for (int c = 0; c < KCHUNKS; c++) {
        int koff = c * TK;
        uint4 ra0 = *(const uint4*)(gA0 + koff + u0l * 8);
        uint4 ra1 = *(const uint4*)(gA1 + koff + u0l * 8);
        uint4 rb0 = v0 ? *(const uint4*)(gB0 + koff + u0l * 8) : make_uint4(0, 0, 0, 0);
        uint4 rb1 = v1 ? *(const uint4*)(gB1 + koff + u0l * 8) : make_uint4(0, 0, 0, 0);

        __syncthreads();   // previous iteration's LDS reads complete
        {
            uint32_t a0 = sw_addr(sA, r0l, u0l), a1 = sw_addr(sA, r1l, u0l);
            uint32_t b0 = sw_addr(sB, r0l, u0l), b1 = sw_addr(sB, r1l, u0l);
            asm volatile("st.shared.v4.b32 [%0], {%1,%2,%3,%4};" :: "r"(a0), "r"(ra0.x), "r"(ra0.y), "r"(ra0.z), "r"(ra0.w) : "memory");
            asm volatile("st.shared.v4.b32 [%0], {%1,%2,%3,%4};" :: "r"(a1), "r"(ra1.x), "r"(ra1.y), "r"(ra1.z), "r"(ra1.w) : "memory");
            asm volatile("st.shared.v4.b32 [%0], {%1,%2,%3,%4};" :: "r"(b0), "r"(rb0.x), "r"(rb0.y), "r"(rb0.z), "r"(rb0.w) : "memory");
            asm volatile("st.shared.v4.b32 [%0], {%1,%2,%3,%4};" :: "r"(b1), "r"(rb1.x), "r"(rb1.y), "r"(rb1.z), "r"(rb1.w) : "memory");
        }
        __syncthreads();   // tile visible to all warps

        // compute: 2 k-steps of 16 (k-units 2s, 2s+1)
#pragma unroll
        for (int s = 0; s < 2; s++) {
            uint32_t aF[4][4];
            uint32_t bF[4][2];
#pragma unroll
            for (int mi = 0; mi < 4; mi++) {
                int r = mbase + mi * 16 + gid;
                aF[mi][0] = lds32(sw_addr(sA, r,     2 * s)     + inoff);
                aF[mi][1] = lds32(sw_addr(sA, r + 8, 2 * s)     + inoff);
                aF[mi][2] = lds32(sw_addr(sA, r,     2 * s + 1) + inoff);
                aF[mi][3] = lds32(sw_addr(sA, r + 8, 2 * s + 1) + inoff);
            }
#pragma unroll
            for (int nj = 0; nj < 4; nj++) {
                int r = nbase + nj * 8 + gid;
                bF[nj][0] = lds32(sw_addr(sB, r, 2 * s)     + inoff);
                bF[nj][1] = lds32(sw_addr(sB, r, 2 * s + 1) + inoff);
            }
#pragma unroll
            for (int mi = 0; mi < 4; mi++)
#pragma unroll
                for (int nj = 0; nj < 4; nj++) {
                    asm volatile(
                        "mma.sync.aligned.m16n8k16.row.col.f32.bf16.bf16.f32 "
                        "{%0,%1,%2,%3}, {%4,%5,%6,%7}, {%8,%9}, {%0,%1,%2,%3};"
                        : "+f"(acc[mi][nj][0]), "+f"(acc[mi][nj][1]),
                          "+f"(acc[mi][nj][2]), "+f"(acc[mi][nj][3])
                        : "r"(aF[mi][0]), "r"(aF[mi][1]), "r"(aF[mi][2]), "r"(aF[mi][3]),
                          "r"(bF[nj][0]), "r"(bF[nj][1]));
                }
        }
    }

    // Epilogue: scale by 1/||e|| and store (float2 per acc pair)
    int rgrp = gid;               // d rows: gid / gid+8
    int cpair = ctid * 2;         // d cols: ctid*2, +1
#pragma unroll
    for (int nj = 0; nj < 4; nj++) {
        int n = n0 + nbase + nj * 8 + cpair;
        if (n >= Nv) continue;    // pair all-or-nothing (Nv even, n even)
        float ri0 = g_rinv[n], ri1 = g_rinv[n + 1];
#pragma unroll
        for (int mi = 0; mi < 4; mi++) {
            int m = m0 + mbase + mi * 16 + rgrp;
            float2 o0 = make_float2(acc[mi][nj][0] * ri0, acc[mi][nj][1] * ri1);
            float2 o1 = make_float2(acc[mi][nj][2] * ri0, acc[mi][nj][3] * ri1);
            *(float2*)(g_sims + (size_t)m * Nv + n) = o0;
            *(float2*)(g_sims + (size_t)(m + 8) * Nv + n) = o1;
        }
    }
}

// ---------------------------------------------------------------------------
// Pass 2: per-row top-TOPC candidate selection (16-bit radix threshold).
// ---------------------------------------------------------------------------
__device__ __forceinline__ unsigned fkey(float f) {
    unsigned u = __float_as_uint(f);
    return (u & 0x80000000u) ? ~u : (u | 0x80000000u);
}

__global__ __launch_bounds__(256) void select_cand_kernel() {
    int b = blockIdx.x;
    int tid = threadIdx.x;
    const float* row = g_sims + (size_t)b * Nv;

    __shared__ unsigned hist[256];
    __shared__ int s_b1, s_above1;
    __shared__ unsigned s_thr;
    __shared__ int s_cnt;

    hist[tid] = 0;
    __syncthreads();
    for (int i = tid; i < Nv; i += 256)
        atomicAdd(&hist[fkey(row[i]) >> 24], 1u);
    __syncthreads();
    if (tid == 0) {
        int run = 0;
        for (int v = 255; v >= 0; v--) {
            run += (int)hist[v];
            if (run >= TOPC) { s_b1 = v; s_above1 = run - (int)hist[v]; break; }
        }
    }
    __syncthreads();
    int b1 = s_b1, above1 = s_above1;

    hist[tid] = 0;
    __syncthreads();
    for (int i = tid; i < Nv; i += 256) {
        unsigned u = fkey(row[i]);
        if ((int)(u >> 24) == b1) atomicAdd(&hist[(u >> 16) & 255u], 1u);
    }
    __syncthreads();
    if (tid == 0) {
        int run = above1;
        s_thr = (unsigned)b1 << 24;
        for (int v = 255; v >= 0; v--) {
            run += (int)hist[v];
            if (run >= TOPC) { s_thr = ((unsigned)b1 << 24) | ((unsigned)v << 16); break; }
        }
        s_cnt = 0;
    }
    __syncthreads();
    unsigned thr = s_thr;

    for (int i = tid; i < Nv; i += 256) {
        if (fkey(row[i]) >= thr) {
            int p = atomicAdd(&s_cnt, 1);
            if (p < CAND_MAX) g_cand[b * CAND_MAX + p] = i;
        }
    }
    __syncthreads();
    if (tid == 0) g_ccnt[b] = (s_cnt < CAND_MAX) ? s_cnt : CAND_MAX;
}

// ---------------------------------------------------------------------------
// Pass 3: exact (double) rescore + exact top-16. One CTA per row.
// ---------------------------------------------------------------------------
__global__ __launch_bounds__(256) void rescore_topk_kernel(const float* __restrict__ X,
                                                           const float* __restrict__ E) {
    int b = blockIdx.x;
    int tid = threadIdx.x;
    int warp = tid >> 5, lane = tid & 31;

    __shared__ float xs[Cv];
    __shared__ double s_sc[CAND_MAX];
    __shared__ int s_id[CAND_MAX];
    __shared__ double wsum[8];
    __shared__ double s_xn2;
    __shared__ double rv[256];
    __shared__ int rslot[256];

    double p = 0.0;
    for (int c = tid; c < Cv; c += 256) {
        float v = X[(size_t)b * Cv + c];
        xs[c] = v;
        p += (double)v * (double)v;
    }
#pragma unroll
    for (int o = 16; o; o >>= 1) p += __shfl_down_sync(0xffffffffu, p, o);
    if (lane == 0) wsum[warp] = p;
    __syncthreads();
    if (tid == 0) {
        double t = 0.0;
        for (int i = 0; i < 8; i++) t += wsum[i];
        s_xn2 = t;
    }
    __syncthreads();

    int cnt = g_ccnt[b];
    for (int ci = warp; ci < cnt; ci += 8) {
        int n = g_cand[b * CAND_MAX + ci];
        const float* er = E + (size_t)n * Cv;
        double d = 0.0, e2 = 0.0;
        for (int c = lane; c < Cv; c += 32) {
            double ev = (double)er[c];
            d = fma((double)xs[c], ev, d);
            e2 = fma(ev, ev, e2);
        }
#pragma unroll
        for (int o = 16; o; o >>= 1) {
            d += __shfl_down_sync(0xffffffffu, d, o);
            e2 += __shfl_down_sync(0xffffffffu, e2, o);
        }
        if (lane == 0) {
            double den = fmax(sqrt(s_xn2) * sqrt(e2), 1e-8);
            s_sc[ci] = d / den;
            s_id[ci] = n;
        }
    }
    for (int ci = cnt + tid; ci < CAND_MAX; ci += 256) {
        s_sc[ci] = -1e300;
        s_id[ci] = 0x7fffffff;
    }
    __syncthreads();

    // exact top-16 over CAND_MAX slots (CAND_MAX=320 > 256: fold tail first)
    for (int r = 0; r < Kv; r++) {
        double bv = s_sc[tid];
        int bs = tid;
        for (int ci = tid + 256; ci < CAND_MAX; ci += 256) {
            double v2 = s_sc[ci];
            if (v2 > bv || (v2 == bv && s_id[ci] < s_id[bs])) { bv = v2; bs = ci; }
        }
        rv[tid] = bv;
        rslot[tid] = bs;
        __syncthreads();
        for (int s = 128; s > 0; s >>= 1) {
            if (tid < s) {
                double v1 = rv[tid], v2 = rv[tid + s];
                int sl1 = rslot[tid], sl2 = rslot[tid + s];
                bool take2 = (v2 > v1) || (v2 == v1 && s_id[sl2] < s_id[sl1]);
                if (take2) { rv[tid] = v2; rslot[tid] = sl2; }
            }
            __syncthreads();
        }
        if (tid == 0) {
            int sl = rslot[0];
            g_topidx[b * Kv + r] = s_id[sl];
            s_sc[sl] = -1e300;
        }
        __syncthreads();
    }
}

// ---------------------------------------------------------------------------
// Pass 4: gather with torch's reshape/permute interleave.
// ---------------------------------------------------------------------------
__global__ __launch_bounds__(192) void gather_kernel(const float* __restrict__ E,
                                                     float* __restrict__ out) {
    int rowi = blockIdx.x;  // rowi = b*Kv + j
    int b = rowi >> 4;
    int j = rowi & 15;
    int src = g_topidx[((j << 7) + (b >> 4)) * Kv + (b & 15)];
    const float4* e4 = (const float4*)(E + (size_t)src * Cv);
    float4* o4 = (float4*)(out + (size_t)rowi * Cv);
    o4[threadIdx.x] = e4[threadIdx.x];
}

// ---------------------------------------------------------------------------
extern "C" void kernel_launch(void* const* d_in, const int* in_sizes, int n_in,
                              void* d_out, int out_size) {
    const float* X = (const float*)d_in[0];  // (B, C)
    const float* E = (const float*)d_in[1];  // (N, C)
    float* out = (float*)d_out;              // (B, k, C)

    // fp32 -> bf16 (globals written inside kernels — never passed as args)
    {
        int n4x = Bv * Cv / 4;
        convert_x_kernel<<<(n4x + 255) / 256, 256>>>(X);
        int n4e = Nv * Cv / 4;
        convert_e_kernel<<<(n4e + 255) / 256, 256>>>(E);
    }
    // E reciprocal norms
    {
        int blocks = (Nv * 32 + 255) / 256;
        norms_kernel<<<blocks, 256>>>(E);
    }
    // bf16 HMMA GEMM -> scaled sims
    {
        dim3 grid(NTILES_N, Bv / TM);
        mma_sims_kernel<<<grid, 256>>>();
    }
    // candidate selection
    select_cand_kernel<<<Bv, 256>>>();
    // exact rescore + top-16
    rescore_topk_kernel<<<Bv, 256>>>(X, E);
    // gather
    gather_kernel<<<Bv * Kv, 192>>>(E, out);
}

// round 7
// speedup vs baseline: 7.2198x; 3.8191x over previous
#include <cuda_runtime.h>
#include <cuda_bf16.h>
#include <math.h>
#include <stdint.h>

// Problem constants
constexpr int Bv = 2048;   // queries
constexpr int Nv = 50000;  // embeddings
constexpr int Cv = 768;    // channels
constexpr int Kv = 16;     // top-k
constexpr int TOPC = 128;      // candidate margin (absorbs bf16 sim error)
constexpr int CAND_MAX = 320;

// GEMM tiling
constexpr int TM = 128, TN = 128, TK = 32;
constexpr int NTILES_N = (Nv + TN - 1) / TN;  // 391
constexpr int KCHUNKS = Cv / TK;              // 24

// Scratch (static __device__ — referenced ONLY from device code; passing a
// __device__ global as a host-side kernel arg is UB — the round-2..5 bug).
__device__ __nv_bfloat16  g_simh[(size_t)Bv * Nv];   // ~205 MB bf16 sims
__device__ __nv_bfloat16  g_Xb[(size_t)Bv * Cv];
__device__ __nv_bfloat16  g_Eb[(size_t)Nv * Cv];
__device__ float          g_rinv[NTILES_N * TN];     // 1/||e_n||, padded
__device__ int            g_cand[Bv * CAND_MAX];
__device__ int            g_ccnt[Bv];
__device__ int            g_topidx[Bv * Kv];

// ---------------------------------------------------------------------------
// fp32 -> bf16 converts (write device globals by direct symbol reference)
// ---------------------------------------------------------------------------
__device__ __forceinline__ uint2 cvt4(const float4 v) {
    __nv_bfloat162 p0 = __float22bfloat162_rn(make_float2(v.x, v.y));
    __nv_bfloat162 p1 = __float22bfloat162_rn(make_float2(v.z, v.w));
    uint2 u;
    u.x = *(uint32_t*)&p0;
    u.y = *(uint32_t*)&p1;
    return u;
}

__global__ void convert_x_kernel(const float* __restrict__ src) {
    int i = blockIdx.x * blockDim.x + threadIdx.x;
    if (i >= Bv * Cv / 4) return;
    ((uint2*)g_Xb)[i] = cvt4(((const float4*)src)[i]);
}

__global__ void convert_e_kernel(const float* __restrict__ src) {
    int i = blockIdx.x * blockDim.x + threadIdx.x;
    if (i >= Nv * Cv / 4) return;
    ((uint2*)g_Eb)[i] = cvt4(((const float4*)src)[i]);
}

// ---------------------------------------------------------------------------
// E row reciprocal norms (fp32). One warp per row.
// ---------------------------------------------------------------------------
__global__ void norms_kernel(const float* __restrict__ E) {
    int gw = (blockIdx.x * blockDim.x + threadIdx.x) >> 5;
    int lane = threadIdx.x & 31;
    if (gw >= Nv) return;
    const float4* r = (const float4*)(E + (size_t)gw * Cv);
    float s = 0.f;
#pragma unroll
    for (int t = 0; t < Cv / 128; t++) {
        float4 v = r[lane + t * 32];
        s = fmaf(v.x, v.x, s); s = fmaf(v.y, v.y, s);
        s = fmaf(v.z, v.z, s); s = fmaf(v.w, v.w, s);
    }
#pragma unroll
    for (int o = 16; o; o >>= 1) s += __shfl_down_sync(0xffffffffu, s, o);
    if (lane == 0) g_rinv[gw] = rsqrtf(s);
}

// ---------------------------------------------------------------------------
// Pass 1: bf16 HMMA GEMM -> bf16 scaled sims (dot * 1/||e||).
// CTA tile 128x128, TK=32, cp.async double buffer, ldmatrix fragments.
// 8 warps (2x4), warp tile 64x32, m16n8k16.
// ---------------------------------------------------------------------------
__device__ __forceinline__ uint32_t smem_u32(const void* p) {
    uint32_t a;
    asm("{ .reg .u64 t; cvta.to.shared.u64 t, %1; cvt.u32.u64 %0, t; }" : "=r"(a) : "l"(p));
    return a;
}

// SMEM addr of (row r, 16B-unit u) within a 128x32 bf16 chunk (64B rows).
__device__ __forceinline__ uint32_t sw_addr(uint32_t base, int r, int u) {
    return base + (uint32_t)r * 64 + (uint32_t)((u ^ ((r >> 1) & 3)) << 4);
}

__device__ __forceinline__ void cpa16(uint32_t dst, const void* src, int sz) {
    asm volatile("cp.async.cg.shared.global [%0], [%1], 16, %2;"
                 :: "r"(dst), "l"(src), "r"(sz) : "memory");
}

__global__ __launch_bounds__(256) void mma_sims_kernel() {
    __shared__ __align__(16) char smem[4 * 8192];  // buf p: A @ p*16384, B @ p*16384+8192
    uint32_t sbase = smem_u32(smem);

    int tid = threadIdx.x;
    int lane = tid & 31, wid = tid >> 5;
    int n0 = blockIdx.x * TN;
    int m0 = blockIdx.y * TM;

    int wm = wid & 1;        // 0..1
    int wn = wid >> 1;       // 0..3
    int mbase = wm * 64;
    int nbase = wn * 32;

    // Global load assignment: (row tid>>2, unit tid&3) and (+64 rows).
    int r0l = tid >> 2, u0l = tid & 3;
    int r1l = r0l + 64;

    int er0 = n0 + r0l, er1 = n0 + r1l;
    int vz0 = (er0 < Nv) ? 16 : 0, vz1 = (er1 < Nv) ? 16 : 0;
    const __nv_bfloat16* gB0 = g_Eb + (size_t)(vz0 ? er0 : 0) * Cv;
    const __nv_bfloat16* gB1 = g_Eb + (size_t)(vz1 ? er1 : 0) * Cv;
    const __nv_bfloat16* gA0 = g_Xb + (size_t)(m0 + r0l) * Cv;
    const __nv_bfloat16* gA1 = g_Xb + (size_t)(m0 + r1l) * Cv;

    float acc[4][4][4];
#pragma unroll
    for (int i = 0; i < 4; i++)
#pragma unroll
        for (int j = 0; j < 4; j++)
#pragma unroll
            for (int q = 0; q < 4; q++) acc[i][j][q] = 0.f;

    // issue one chunk's loads into buffer p
    auto load_chunk = [&](int c, int p) {
        int koff = c * TK + u0l * 8;
        uint32_t ab = sbase + p * 16384;
        uint32_t bb = ab + 8192;
        cpa16(sw_addr(ab, r0l, u0l), gA0 + koff, 16);
        cpa16(sw_addr(ab, r1l, u0l), gA1 + koff, 16);
        cpa16(sw_addr(bb, r0l, u0l), gB0 + koff, vz0);
        cpa16(sw_addr(bb, r1l, u0l), gB1 + koff, vz1);
        asm volatile("cp.async.commit_group;" ::: "memory");
    };

    load_chunk(0, 0);
    load_chunk(1, 1);

    for (int c = 0; c < KCHUNKS; c++) {
        if (c + 1 < KCHUNKS)
            asm volatile("cp.async.wait_group 1;" ::: "memory");
        else
            asm volatile("cp.async.wait_group 0;" ::: "memory");
        __syncthreads();

        uint32_t bufA = sbase + (c & 1) * 16384;
        uint32_t bufB = bufA + 8192;

#pragma unroll
        for (int s = 0; s < 2; s++) {
            int u0 = 2 * s;
            uint32_t aF[4][4];
            uint32_t bF[4][2];
#pragma unroll
            for (int mi = 0; mi < 4; mi++) {
                int r = mbase + mi * 16 + (lane & 15);
                int u = u0 + (lane >> 4);
                uint32_t addr = sw_addr(bufA, r, u);
                asm volatile("ldmatrix.sync.aligned.m8n8.x4.shared.b16 {%0,%1,%2,%3}, [%4];"
                             : "=r"(aF[mi][0]), "=r"(aF[mi][1]), "=r"(aF[mi][2]), "=r"(aF[mi][3])
                             : "r"(addr));
            }
#pragma unroll
            for (int q = 0; q < 2; q++) {
                int r = nbase + q * 16 + ((lane >> 4) << 3) + (lane & 7);
                int u = u0 + ((lane >> 3) & 1);
                uint32_t addr = sw_addr(bufB, r, u);
                uint32_t f0, f1, f2, f3;
                asm volatile("ldmatrix.sync.aligned.m8n8.x4.shared.b16 {%0,%1,%2,%3}, [%4];"
                             : "=r"(f0), "=r"(f1), "=r"(f2), "=r"(f3)
                             : "r"(addr));
                bF[q * 2 + 0][0] = f0; bF[q * 2 + 0][1] = f1;
                bF[q * 2 + 1][0] = f2; bF[q * 2 + 1][1] = f3;
            }
#pragma unroll
            for (int mi = 0; mi < 4; mi++)
#pragma unroll
                for (int nj = 0; nj < 4; nj++) {
                    asm volatile(
                        "mma.sync.aligned.m16n8k16.row.col.f32.bf16.bf16.f32 "
                        "{%0,%1,%2,%3}, {%4,%5,%6,%7}, {%8,%9}, {%0,%1,%2,%3};"
                        : "+f"(acc[mi][nj][0]), "+f"(acc[mi][nj][1]),
                          "+f"(acc[mi][nj][2]), "+f"(acc[mi][nj][3])
                        : "r"(aF[mi][0]), "r"(aF[mi][1]), "r"(aF[mi][2]), "r"(aF[mi][3]),
                          "r"(bF[nj][0]), "r"(bF[nj][1]));
                }
        }
        __syncthreads();
        if (c + 2 < KCHUNKS) load_chunk(c + 2, c & 1);
    }

    // Epilogue: scale by 1/||e||, convert to bf16 pair, store as uint32
    int gid = lane >> 2;
    int cpair = (lane & 3) * 2;
#pragma unroll
    for (int nj = 0; nj < 4; nj++) {
        int n = n0 + nbase + nj * 8 + cpair;
        if (n >= Nv) continue;    // pair all-or-nothing (Nv even, n even)
        float ri0 = g_rinv[n], ri1 = g_rinv[n + 1];
#pragma unroll
        for (int mi = 0; mi < 4; mi++) {
            int m = m0 + mbase + mi * 16 + gid;
            __nv_bfloat162 h0 = __float22bfloat162_rn(
                make_float2(acc[mi][nj][0] * ri0, acc[mi][nj][1] * ri1));
            __nv_bfloat162 h1 = __float22bfloat162_rn(
                make_float2(acc[mi][nj][2] * ri0, acc[mi][nj][3] * ri1));
            *(uint32_t*)(g_simh + (size_t)m * Nv + n) = *(uint32_t*)&h0;
            *(uint32_t*)(g_simh + (size_t)(m + 8) * Nv + n) = *(uint32_t*)&h1;
        }
    }
}

// ---------------------------------------------------------------------------
// Pass 2: per-row top-TOPC candidate selection (16-bit radix threshold on
// bf16 keys). One CTA per row; reads packed uint32 (2 bf16).
// ---------------------------------------------------------------------------
__device__ __forceinline__ uint32_t fkey16(uint32_t h) {  // h: bf16 bits in low 16
    return (h & 0x8000u) ? ((~h) & 0xFFFFu) : (h | 0x8000u);
}

__global__ __launch_bounds__(256) void select_cand_kernel() {
    int b = blockIdx.x;
    int tid = threadIdx.x;
    const uint32_t* row = (const uint32_t*)(g_simh + (size_t)b * Nv);
    constexpr int NW = Nv / 2;  // 25000 packed words

    __shared__ unsigned hist[256];
    __shared__ int s_b1, s_above1;
    __shared__ uint32_t s_thr;
    __shared__ int s_cnt;

    // --- pass 1: histogram of top 8 bits of 16-bit key ---
    hist[tid] = 0;
    __syncthreads();
    for (int w = tid; w < NW; w += 256) {
        uint32_t u = row[w];
        atomicAdd(&hist[fkey16(u & 0xFFFFu) >> 8], 1u);
        atomicAdd(&hist[fkey16(u >> 16) >> 8], 1u);
    }
    __syncthreads();
    if (tid == 0) {
        int run = 0;
        for (int v = 255; v >= 0; v--) {
            run += (int)hist[v];
            if (run >= TOPC) { s_b1 = v; s_above1 = run - (int)hist[v]; break; }
        }
    }
    __syncthreads();
    int b1 = s_b1, above1 = s_above1;

    // --- pass 2: histogram of low 8 bits within bin b1 ---
    hist[tid] = 0;
    __syncthreads();
    for (int w = tid; w < NW; w += 256) {
        uint32_t u = row[w];
        uint32_t k0 = fkey16(u & 0xFFFFu), k1 = fkey16(u >> 16);
        if ((int)(k0 >> 8) == b1) atomicAdd(&hist[k0 & 255u], 1u);
        if ((int)(k1 >> 8) == b1) atomicAdd(&hist[k1 & 255u], 1u);
    }
    __syncthreads();
    if (tid == 0) {
        int run = above1;
        s_thr = (uint32_t)b1 << 8;
        for (int v = 255; v >= 0; v--) {
            run += (int)hist[v];
            if (run >= TOPC) { s_thr = ((uint32_t)b1 << 8) | (uint32_t)v; break; }
        }
        s_cnt = 0;
    }
    __syncthreads();
    uint32_t thr = s_thr;

    // --- collect candidates with key >= thr ---
    for (int w = tid; w < NW; w += 256) {
        uint32_t u = row[w];
        if (fkey16(u & 0xFFFFu) >= thr) {
            int p = atomicAdd(&s_cnt, 1);
            if (p < CAND_MAX) g_cand[b * CAND_MAX + p] = 2 * w;
        }
        if (fkey16(u >> 16) >= thr) {
            int p = atomicAdd(&s_cnt, 1);
            if (p < CAND_MAX) g_cand[b * CAND_MAX + p] = 2 * w + 1;
        }
    }
    __syncthreads();
    if (tid == 0) g_ccnt[b] = (s_cnt < CAND_MAX) ? s_cnt : CAND_MAX;
}

// ---------------------------------------------------------------------------
// Pass 3: fp32 rescore (dot * 1/||e||; x-norm is a row constant — rank-
// invariant) + exact top-16. One CTA (8 warps) per row, warp per candidate.
// ---------------------------------------------------------------------------
__global__ __launch_bounds__(256) void rescore_topk_kernel(const float* __restrict__ X,
                                                           const float* __restrict__ E) {
    int b = blockIdx.x;
    int tid = threadIdx.x;
    int warp = tid >> 5, lane = tid & 31;

    __shared__ float xs[Cv];
    __shared__ float s_sc[CAND_MAX];
    __shared__ int s_id[CAND_MAX];
    __shared__ float rv[256];
    __shared__ int rslot[256];

    for (int c = tid; c < Cv; c += 256) xs[c] = X[(size_t)b * Cv + c];
    __syncthreads();

    int cnt = g_ccnt[b];
    const float4* xs4 = (const float4*)xs;
    for (int ci = warp; ci < cnt; ci += 8) {
        int n = g_cand[b * CAND_MAX + ci];
        const float4* er = (const float4*)(E + (size_t)n * Cv);
        float d = 0.f;
#pragma unroll
        for (int j = 0; j < Cv / 128; j++) {
            float4 e = er[lane + j * 32];
            float4 x = xs4[lane + j * 32];
            d = fmaf(x.x, e.x, d); d = fmaf(x.y, e.y, d);
            d = fmaf(x.z, e.z, d); d = fmaf(x.w, e.w, d);
        }
#pragma unroll
        for (int o = 16; o; o >>= 1) d += __shfl_down_sync(0xffffffffu, d, o);
        if (lane == 0) {
            s_sc[ci] = d * g_rinv[n];
            s_id[ci] = n;
        }
    }
    for (int ci = cnt + tid; ci < CAND_MAX; ci += 256) {
        s_sc[ci] = -1e30f;
        s_id[ci] = 0x7fffffff;
    }
    __syncthreads();

    // exact top-16, descending, tie-break smaller index (CAND_MAX>256: fold)
    for (int r = 0; r < Kv; r++) {
        float bv = s_sc[tid];
        int bs = tid;
        for (int ci = tid + 256; ci < CAND_MAX; ci += 256) {
            float v2 = s_sc[ci];
            if (v2 > bv || (v2 == bv && s_id[ci] < s_id[bs])) { bv = v2; bs = ci; }
        }
        rv[tid] = bv;
        rslot[tid] = bs;
        __syncthreads();
        for (int s = 128; s > 0; s >>= 1) {
            if (tid < s) {
                float v1 = rv[tid], v2 = rv[tid + s];
                int sl1 = rslot[tid], sl2 = rslot[tid + s];
                bool take2 = (v2 > v1) || (v2 == v1 && s_id[sl2] < s_id[sl1]);
                if (take2) { rv[tid] = v2; rslot[tid] = sl2; }
            }
            __syncthreads();
        }
        if (tid == 0) {
            int sl = rslot[0];
            g_topidx[b * Kv + r] = s_id[sl];
            s_sc[sl] = -1e30f;
        }
        __syncthreads();
    }
}

// ---------------------------------------------------------------------------
// Pass 4: gather with torch's reshape/permute interleave.
// ---------------------------------------------------------------------------
__global__ __launch_bounds__(192) void gather_kernel(const float* __restrict__ E,
                                                     float* __restrict__ out) {
    int rowi = blockIdx.x;  // rowi = b*Kv + j
    int b = rowi >> 4;
    int j = rowi & 15;
    int src = g_topidx[((j << 7) + (b >> 4)) * Kv + (b & 15)];
    const float4* e4 = (const float4*)(E + (size_t)src * Cv);
    float4* o4 = (float4*)(out + (size_t)rowi * Cv);
    o4[threadIdx.x] = e4[threadIdx.x];
}

// ---------------------------------------------------------------------------
extern "C" void kernel_launch(void* const* d_in, const int* in_sizes, int n_in,
                              void* d_out, int out_size) {
    const float* X = (const float*)d_in[0];  // (B, C)
    const float* E = (const float*)d_in[1];  // (N, C)
    float* out = (float*)d_out;              // (B, k, C)

    {
        int n4x = Bv * Cv / 4;
        convert_x_kernel<<<(n4x + 255) / 256, 256>>>(X);
        int n4e = Nv * Cv / 4;
        convert_e_kernel<<<(n4e + 255) / 256, 256>>>(E);
    }
    {
        int blocks = (Nv * 32 + 255) / 256;
        norms_kernel<<<blocks, 256>>>(E);
    }
    {
        dim3 grid(NTILES_N, Bv / TM);
        mma_sims_kernel<<<grid, 256>>>();
    }
    select_cand_kernel<<<Bv, 256>>>();
    rescore_topk_kernel<<<Bv, 256>>>(X, E);
    gather_kernel<<<Bv * Kv, 192>>>(E, out);
}

// round 8
// speedup vs baseline: 7.7745x; 1.0768x over previous
#include <cuda_runtime.h>
#include <cuda_bf16.h>
#include <math.h>
#include <stdint.h>

// Problem constants
constexpr int Bv = 2048;   // queries
constexpr int Nv = 50000;  // embeddings
constexpr int Cv = 768;    // channels
constexpr int Kv = 16;     // top-k
constexpr int TOPC = 128;      // candidate margin (absorbs bf16 sim error)
constexpr int CAND_MAX = 512;  // bin-granular threshold => extra candidates

// GEMM tiling
constexpr int TM = 128, TN = 128, TK = 32;
constexpr int NTILES_N = (Nv + TN - 1) / TN;  // 391
constexpr int KCHUNKS = Cv / TK;              // 24
constexpr int STAGES = 3;

// Scratch (static __device__ — referenced ONLY from device code; passing a
// __device__ global as a host-side kernel arg is UB — the round-2..5 bug).
__device__ __nv_bfloat16  g_simh[(size_t)Bv * Nv];   // ~205 MB bf16 sims
__device__ __nv_bfloat16  g_Xb[(size_t)Bv * Cv];
__device__ __nv_bfloat16  g_Eb[(size_t)Nv * Cv];
__device__ float          g_rinv[NTILES_N * TN];     // 1/||e_n||, padded
__device__ int            g_cand[Bv * CAND_MAX];
__device__ int            g_ccnt[Bv];
__device__ int            g_topidx[Bv * Kv];

// ---------------------------------------------------------------------------
// X: fp32 -> bf16 convert
// ---------------------------------------------------------------------------
__device__ __forceinline__ uint2 cvt4(const float4 v) {
    __nv_bfloat162 p0 = __float22bfloat162_rn(make_float2(v.x, v.y));
    __nv_bfloat162 p1 = __float22bfloat162_rn(make_float2(v.z, v.w));
    uint2 u;
    u.x = *(uint32_t*)&p0;
    u.y = *(uint32_t*)&p1;
    return u;
}

__global__ void convert_x_kernel(const float* __restrict__ src) {
    int i = blockIdx.x * blockDim.x + threadIdx.x;
    if (i >= Bv * Cv / 4) return;
    ((uint2*)g_Xb)[i] = cvt4(((const float4*)src)[i]);
}

// ---------------------------------------------------------------------------
// E: fused fp32->bf16 convert + reciprocal norm. One warp per row.
// ---------------------------------------------------------------------------
__global__ void convert_e_norms_kernel(const float* __restrict__ E) {
    int gw = (blockIdx.x * blockDim.x + threadIdx.x) >> 5;
    int lane = threadIdx.x & 31;
    if (gw >= Nv) return;
    const float4* r = (const float4*)(E + (size_t)gw * Cv);
    uint2* drow = (uint2*)(g_Eb + (size_t)gw * Cv);
    float s = 0.f;
#pragma unroll
    for (int t = 0; t < Cv / 128; t++) {
        float4 v = r[lane + t * 32];
        drow[lane + t * 32] = cvt4(v);
        s = fmaf(v.x, v.x, s); s = fmaf(v.y, v.y, s);
        s = fmaf(v.z, v.z, s); s = fmaf(v.w, v.w, s);
    }
#pragma unroll
    for (int o = 16; o; o >>= 1) s += __shfl_down_sync(0xffffffffu, s, o);
    if (lane == 0) g_rinv[gw] = rsqrtf(s);
}

// ---------------------------------------------------------------------------
// Pass 1: bf16 HMMA GEMM -> bf16 scaled sims (dot * 1/||e||).
// CTA tile 128x128, TK=32, 3-stage cp.async, ONE syncthreads per chunk.
// 8 warps (2x4), warp tile 64x32, m16n8k16, ldmatrix fragments.
// ---------------------------------------------------------------------------
__device__ __forceinline__ uint32_t smem_u32(const void* p) {
    uint32_t a;
    asm("{ .reg .u64 t; cvta.to.shared.u64 t, %1; cvt.u32.u64 %0, t; }" : "=r"(a) : "l"(p));
    return a;
}

// SMEM addr of (row r, 16B-unit u) within a 128x32 bf16 chunk (64B rows).
__device__ __forceinline__ uint32_t sw_addr(uint32_t base, int r, int u) {
    return base + (uint32_t)r * 64 + (uint32_t)((u ^ ((r >> 1) & 3)) << 4);
}

__device__ __forceinline__ void cpa16(uint32_t dst, const void* src, int sz) {
    asm volatile("cp.async.cg.shared.global [%0], [%1], 16, %2;"
                 :: "r"(dst), "l"(src), "r"(sz) : "memory");
}

__global__ __launch_bounds__(256) void mma_sims_kernel() {
    // 3 stages x (A 8KB + B 8KB) = 49152 bytes (static 48KB limit, exactly)
    __shared__ __align__(16) char smem[STAGES * 16384];
    uint32_t sbase = smem_u32(smem);

    int tid = threadIdx.x;
    int lane = tid & 31, wid = tid >> 5;
    int n0 = blockIdx.x * TN;
    int m0 = blockIdx.y * TM;

    int wm = wid & 1;
    int wn = wid >> 1;
    int mbase = wm * 64;
    int nbase = wn * 32;

    // Global load assignment: (row tid>>2, unit tid&3) and (+64 rows).
    int r0l = tid >> 2, u0l = tid & 3;
    int r1l = r0l + 64;

    int er0 = n0 + r0l, er1 = n0 + r1l;
    int vz0 = (er0 < Nv) ? 16 : 0, vz1 = (er1 < Nv) ? 16 : 0;
    const __nv_bfloat16* gB0 = g_Eb + (size_t)(vz0 ? er0 : 0) * Cv;
    const __nv_bfloat16* gB1 = g_Eb + (size_t)(vz1 ? er1 : 0) * Cv;
    const __nv_bfloat16* gA0 = g_Xb + (size_t)(m0 + r0l) * Cv;
    const __nv_bfloat16* gA1 = g_Xb + (size_t)(m0 + r1l) * Cv;

    float acc[4][4][4];
#pragma unroll
    for (int i = 0; i < 4; i++)
#pragma unroll
        for (int j = 0; j < 4; j++)
#pragma unroll
            for (int q = 0; q < 4; q++) acc[i][j][q] = 0.f;

    auto load_chunk = [&](int c, int p) {
        int koff = c * TK + u0l * 8;
        uint32_t ab = sbase + p * 16384;
        uint32_t bb = ab + 8192;
        cpa16(sw_addr(ab, r0l, u0l), gA0 + koff, 16);
        cpa16(sw_addr(ab, r1l, u0l), gA1 + koff, 16);
        cpa16(sw_addr(bb, r0l, u0l), gB0 + koff, vz0);
        cpa16(sw_addr(bb, r1l, u0l), gB1 + koff, vz1);
        asm volatile("cp.async.commit_group;" ::: "memory");
    };

    load_chunk(0, 0);
    load_chunk(1, 1);

    int buf = 0;
    for (int c = 0; c < KCHUNKS; c++) {
        if (c + 1 < KCHUNKS)
            asm volatile("cp.async.wait_group 1;" ::: "memory");
        else
            asm volatile("cp.async.wait_group 0;" ::: "memory");
        __syncthreads();   // single barrier per chunk (3-stage makes it safe)

        uint32_t bufA = sbase + buf * 16384;
        uint32_t bufB = bufA + 8192;

#pragma unroll
        for (int s = 0; s < 2; s++) {
            int u0 = 2 * s;
            uint32_t aF[4][4];
            uint32_t bF[4][2];
#pragma unroll
            for (int mi = 0; mi < 4; mi++) {
                int r = mbase + mi * 16 + (lane & 15);
                int u = u0 + (lane >> 4);
                uint32_t addr = sw_addr(bufA, r, u);
                asm volatile("ldmatrix.sync.aligned.m8n8.x4.shared.b16 {%0,%1,%2,%3}, [%4];"
                             : "=r"(aF[mi][0]), "=r"(aF[mi][1]), "=r"(aF[mi][2]), "=r"(aF[mi][3])
                             : "r"(addr));
            }
#pragma unroll
            for (int q = 0; q < 2; q++) {
                int r = nbase + q * 16 + ((lane >> 4) << 3) + (lane & 7);
                int u = u0 + ((lane >> 3) & 1);
                uint32_t addr = sw_addr(bufB, r, u);
                uint32_t f0, f1, f2, f3;
                asm volatile("ldmatrix.sync.aligned.m8n8.x4.shared.b16 {%0,%1,%2,%3}, [%4];"
                             : "=r"(f0), "=r"(f1), "=r"(f2), "=r"(f3)
                             : "r"(addr));
                bF[q * 2 + 0][0] = f0; bF[q * 2 + 0][1] = f1;
                bF[q * 2 + 1][0] = f2; bF[q * 2 + 1][1] = f3;
            }
#pragma unroll
            for (int mi = 0; mi < 4; mi++)
#pragma unroll
                for (int nj = 0; nj < 4; nj++) {
                    asm volatile(
                        "mma.sync.aligned.m16n8k16.row.col.f32.bf16.bf16.f32 "
                        "{%0,%1,%2,%3}, {%4,%5,%6,%7}, {%8,%9}, {%0,%1,%2,%3};"
                        : "+f"(acc[mi][nj][0]), "+f"(acc[mi][nj][1]),
                          "+f"(acc[mi][nj][2]), "+f"(acc[mi][nj][3])
                        : "r"(aF[mi][0]), "r"(aF[mi][1]), "r"(aF[mi][2]), "r"(aF[mi][3]),
                          "r"(bF[nj][0]), "r"(bF[nj][1]));
                }
        }

        if (c + 2 < KCHUNKS) load_chunk(c + 2, (c + 2) % STAGES);
        buf = (buf + 1 == STAGES) ? 0 : buf + 1;
    }

    // Epilogue: scale by 1/||e||, convert to bf16 pair, store as uint32
    int gid = lane >> 2;
    int cpair = (lane & 3) * 2;
#pragma unroll
    for (int nj = 0; nj < 4; nj++) {
        int n = n0 + nbase + nj * 8 + cpair;
        if (n >= Nv) continue;    // pair all-or-nothing (Nv even, n even)
        float ri0 = g_rinv[n], ri1 = g_rinv[n + 1];
#pragma unroll
        for (int mi = 0; mi < 4; mi++) {
            int m = m0 + mbase + mi * 16 + gid;
            __nv_bfloat162 h0 = __float22bfloat162_rn(
                make_float2(acc[mi][nj][0] * ri0, acc[mi][nj][1] * ri1));
            __nv_bfloat162 h1 = __float22bfloat162_rn(
                make_float2(acc[mi][nj][2] * ri0, acc[mi][nj][3] * ri1));
            *(uint32_t*)(g_simh + (size_t)m * Nv + n) = *(uint32_t*)&h0;
            *(uint32_t*)(g_simh + (size_t)(m + 8) * Nv + n) = *(uint32_t*)&h1;
        }
    }
}

// ---------------------------------------------------------------------------
// Pass 2: per-row candidate selection, TWO passes over the row:
// 12-bit-prefix histogram (4096 bins) -> threshold bin -> collect.
// One CTA per row; uint4 reads (8 bf16 each).
// ---------------------------------------------------------------------------
__device__ __forceinline__ uint32_t fkey16(uint32_t h) {  // bf16 bits (low 16)
    return (h & 0x8000u) ? ((~h) & 0xFFFFu) : (h | 0x8000u);
}

__global__ __launch_bounds__(256) void select_cand_kernel() {
    int b = blockIdx.x;
    int tid = threadIdx.x;
    const uint4* row = (const uint4*)(g_simh + (size_t)b * Nv);
    constexpr int NW = Nv / 8;  // 6250 uint4

    __shared__ unsigned hist[4096];
    __shared__ unsigned coarse[256];
    __shared__ uint32_t s_thr;
    __shared__ int s_cnt;

#pragma unroll
    for (int i = 0; i < 16; i++) hist[tid + i * 256] = 0;
    __syncthreads();

    // --- pass 1: histogram of top 12 bits of the 16-bit key ---
    for (int w = tid; w < NW; w += 256) {
        uint4 u = row[w];
        atomicAdd(&hist[fkey16(u.x & 0xFFFFu) >> 4], 1u);
        atomicAdd(&hist[fkey16(u.x >> 16) >> 4], 1u);
        atomicAdd(&hist[fkey16(u.y & 0xFFFFu) >> 4], 1u);
        atomicAdd(&hist[fkey16(u.y >> 16) >> 4], 1u);
        atomicAdd(&hist[fkey16(u.z & 0xFFFFu) >> 4], 1u);
        atomicAdd(&hist[fkey16(u.z >> 16) >> 4], 1u);
        atomicAdd(&hist[fkey16(u.w & 0xFFFFu) >> 4], 1u);
        atomicAdd(&hist[fkey16(u.w >> 16) >> 4], 1u);
    }
    __syncthreads();

    // two-level threshold scan
    {
        unsigned cs = 0;
#pragma unroll
        for (int i = 0; i < 16; i++) cs += hist[tid * 16 + i];
        coarse[tid] = cs;
    }
    __syncthreads();
    if (tid == 0) {
        int run = 0, cb = 0;
        for (int v = 255; v >= 0; v--) {
            run += (int)coarse[v];
            if (run >= TOPC) { cb = v; run -= (int)coarse[v]; break; }
        }
        int fb = cb * 16;  // fallback: whole coarse bin
        for (int f = 15; f >= 0; f--) {
            run += (int)hist[cb * 16 + f];
            if (run >= TOPC) { fb = cb * 16 + f; break; }
        }
        s_thr = (uint32_t)fb << 4;
        s_cnt = 0;
    }
    __syncthreads();
    uint32_t thr = s_thr;

    // --- pass 2: collect candidates with key >= thr ---
    for (int w = tid; w < NW; w += 256) {
        uint4 u = row[w];
        uint32_t h[8] = {u.x & 0xFFFFu, u.x >> 16, u.y & 0xFFFFu, u.y >> 16,
                         u.z & 0xFFFFu, u.z >> 16, u.w & 0xFFFFu, u.w >> 16};
#pragma unroll
        for (int i = 0; i < 8; i++) {
            if (fkey16(h[i]) >= thr) {
                int p = atomicAdd(&s_cnt, 1);
                if (p < CAND_MAX) g_cand[b * CAND_MAX + p] = 8 * w + i;
            }
        }
    }
    __syncthreads();
    if (tid == 0) g_ccnt[b] = (s_cnt < CAND_MAX) ? s_cnt : CAND_MAX;
}

// ---------------------------------------------------------------------------
// Pass 3: fp32 rescore (dot * 1/||e||; x-norm is a positive row constant —
// rank-invariant) + exact top-16. One CTA (8 warps) per row.
// ---------------------------------------------------------------------------
__global__ __launch_bounds__(256) void rescore_topk_kernel(const float* __restrict__ X,
                                                           const float* __restrict__ E) {
    int b = blockIdx.x;
    int tid = threadIdx.x;
    int warp = tid >> 5, lane = tid & 31;

    __shared__ float xs[Cv];
    __shared__ float s_sc[CAND_MAX];
    __shared__ int s_id[CAND_MAX];
    __shared__ float rv[256];
    __shared__ int rslot[256];

    for (int c = tid; c < Cv; c += 256) xs[c] = X[(size_t)b * Cv + c];
    __syncthreads();

    int cnt = g_ccnt[b];
    const float4* xs4 = (const float4*)xs;
    for (int ci = warp; ci < cnt; ci += 8) {
        int n = g_cand[b * CAND_MAX + ci];
        const float4* er = (const float4*)(E + (size_t)n * Cv);
        float d = 0.f;
#pragma unroll
        for (int j = 0; j < Cv / 128; j++) {
            float4 e = er[lane + j * 32];
            float4 x = xs4[lane + j * 32];
            d = fmaf(x.x, e.x, d); d = fmaf(x.y, e.y, d);
            d = fmaf(x.z, e.z, d); d = fmaf(x.w, e.w, d);
        }
#pragma unroll
        for (int o = 16; o; o >>= 1) d += __shfl_down_sync(0xffffffffu, d, o);
        if (lane == 0) {
            s_sc[ci] = d * g_rinv[n];
            s_id[ci] = n;
        }
    }
    for (int ci = cnt + tid; ci < CAND_MAX; ci += 256) {
        s_sc[ci] = -1e30f;
        s_id[ci] = 0x7fffffff;
    }
    __syncthreads();

    // exact top-16, descending, tie-break smaller index (fold 512 -> 256)
    for (int r = 0; r < Kv; r++) {
        float bv = s_sc[tid];
        int bs = tid;
        {
            float v2 = s_sc[tid + 256];
            if (v2 > bv || (v2 == bv && s_id[tid + 256] < s_id[bs])) { bv = v2; bs = tid + 256; }
        }
        rv[tid] = bv;
        rslot[tid] = bs;
        __syncthreads();
        for (int s = 128; s > 0; s >>= 1) {
            if (tid < s) {
                float v1 = rv[tid], v2 = rv[tid + s];
                int sl1 = rslot[tid], sl2 = rslot[tid + s];
                bool take2 = (v2 > v1) || (v2 == v1 && s_id[sl2] < s_id[sl1]);
                if (take2) { rv[tid] = v2; rslot[tid] = sl2; }
            }
            __syncthreads();
        }
        if (tid == 0) {
            int sl = rslot[0];
            g_topidx[b * Kv + r] = s_id[sl];
            s_sc[sl] = -1e30f;
        }
        __syncthreads();
    }
}

// ---------------------------------------------------------------------------
// Pass 4: gather with torch's reshape/permute interleave.
// ---------------------------------------------------------------------------
__global__ __launch_bounds__(192) void gather_kernel(const float* __restrict__ E,
                                                     float* __restrict__ out) {
    int rowi = blockIdx.x;  // rowi = b*Kv + j
    int b = rowi >> 4;
    int j = rowi & 15;
    int src = g_topidx[((j << 7) + (b >> 4)) * Kv + (b & 15)];
    const float4* e4 = (const float4*)(E + (size_t)src * Cv);
    float4* o4 = (float4*)(out + (size_t)rowi * Cv);
    o4[threadIdx.x] = e4[threadIdx.x];
}

// ---------------------------------------------------------------------------
extern "C" void kernel_launch(void* const* d_in, const int* in_sizes, int n_in,
                              void* d_out, int out_size) {
    const float* X = (const float*)d_in[0];  // (B, C)
    const float* E = (const float*)d_in[1];  // (N, C)
    float* out = (float*)d_out;              // (B, k, C)

    {
        int n4x = Bv * Cv / 4;
        convert_x_kernel<<<(n4x + 255) / 256, 256>>>(X);
        int blocks = (Nv * 32 + 255) / 256;
        convert_e_norms_kernel<<<blocks, 256>>>(E);
    }
    {
        dim3 grid(NTILES_N, Bv / TM);
        mma_sims_kernel<<<grid, 256>>>();
    }
    select_cand_kernel<<<Bv, 256>>>();
    rescore_topk_kernel<<<Bv, 256>>>(X, E);
    gather_kernel<<<Bv * Kv, 192>>>(E, out);
}

// round 9
// speedup vs baseline: 7.7792x; 1.0006x over previous
#include <cuda_runtime.h>
#include <cuda_bf16.h>
#include <math.h>
#include <stdint.h>

// Problem constants
constexpr int Bv = 2048;   // queries
constexpr int Nv = 50000;  // embeddings
constexpr int Cv = 768;    // channels
constexpr int Kv = 16;     // top-k
constexpr int TOPC = 128;      // candidate margin (absorbs bf16 sim error)
constexpr int CAND_MAX = 512;  // bin-granular threshold => extra candidates

// GEMM tiling
constexpr int TM = 128, TN = 128, TK = 32;
constexpr int NTILES_N = (Nv + TN - 1) / TN;  // 391
constexpr int KCHUNKS = Cv / TK;              // 24
constexpr int STAGES = 3;

// Scratch (static __device__ — referenced ONLY from device code; passing a
// __device__ global as a host-side kernel arg is UB — the round-2..5 bug).
__device__ __nv_bfloat16  g_simh[(size_t)Bv * Nv];   // ~205 MB bf16 sims
__device__ __nv_bfloat16  g_Xb[(size_t)Bv * Cv];
__device__ __nv_bfloat16  g_Eb[(size_t)Nv * Cv];
__device__ float          g_rinv[NTILES_N * TN];     // 1/||e_n||, padded
__device__ int            g_cand[Bv * CAND_MAX];
__device__ int            g_ccnt[Bv];
__device__ int            g_topidx[Bv * Kv];

// ---------------------------------------------------------------------------
// X: fp32 -> bf16 convert
// ---------------------------------------------------------------------------
__device__ __forceinline__ uint2 cvt4(const float4 v) {
    __nv_bfloat162 p0 = __float22bfloat162_rn(make_float2(v.x, v.y));
    __nv_bfloat162 p1 = __float22bfloat162_rn(make_float2(v.z, v.w));
    uint2 u;
    u.x = *(uint32_t*)&p0;
    u.y = *(uint32_t*)&p1;
    return u;
}

__global__ void convert_x_kernel(const float* __restrict__ src) {
    int i = blockIdx.x * blockDim.x + threadIdx.x;
    if (i >= Bv * Cv / 4) return;
    ((uint2*)g_Xb)[i] = cvt4(((const float4*)src)[i]);
}

// ---------------------------------------------------------------------------
// E: fused fp32->bf16 convert + reciprocal norm. One warp per row.
// ---------------------------------------------------------------------------
__global__ void convert_e_norms_kernel(const float* __restrict__ E) {
    int gw = (blockIdx.x * blockDim.x + threadIdx.x) >> 5;
    int lane = threadIdx.x & 31;
    if (gw >= Nv) return;
    const float4* r = (const float4*)(E + (size_t)gw * Cv);
    uint2* drow = (uint2*)(g_Eb + (size_t)gw * Cv);
    float s = 0.f;
#pragma unroll
    for (int t = 0; t < Cv / 128; t++) {
        float4 v = r[lane + t * 32];
        drow[lane + t * 32] = cvt4(v);
        s = fmaf(v.x, v.x, s); s = fmaf(v.y, v.y, s);
        s = fmaf(v.z, v.z, s); s = fmaf(v.w, v.w, s);
    }
#pragma unroll
    for (int o = 16; o; o >>= 1) s += __shfl_down_sync(0xffffffffu, s, o);
    if (lane == 0) g_rinv[gw] = rsqrtf(s);
}

// ---------------------------------------------------------------------------
// Pass 1: bf16 HMMA GEMM -> bf16 scaled sims (dot * 1/||e||).
// CTA tile 128x128, TK=32, 3-stage cp.async, ONE syncthreads per chunk.
// 8 warps (2x4), warp tile 64x32, m16n8k16, ldmatrix fragments.
// ---------------------------------------------------------------------------
__device__ __forceinline__ uint32_t smem_u32(const void* p) {
    uint32_t a;
    asm("{ .reg .u64 t; cvta.to.shared.u64 t, %1; cvt.u32.u64 %0, t; }" : "=r"(a) : "l"(p));
    return a;
}

// SMEM addr of (row r, 16B-unit u) within a 128x32 bf16 chunk (64B rows).
__device__ __forceinline__ uint32_t sw_addr(uint32_t base, int r, int u) {
    return base + (uint32_t)r * 64 + (uint32_t)((u ^ ((r >> 1) & 3)) << 4);
}

__device__ __forceinline__ void cpa16(uint32_t dst, const void* src, int sz) {
    asm volatile("cp.async.cg.shared.global [%0], [%1], 16, %2;"
                 :: "r"(dst), "l"(src), "r"(sz) : "memory");
}

__global__ __launch_bounds__(256) void mma_sims_kernel() {
    // 3 stages x (A 8KB + B 8KB) = 49152 bytes (static 48KB limit, exactly)
    __shared__ __align__(16) char smem[STAGES * 16384];
    uint32_t sbase = smem_u32(smem);

    int tid = threadIdx.x;
    int lane = tid & 31, wid = tid >> 5;
    int n0 = blockIdx.x * TN;
    int m0 = blockIdx.y * TM;

    int wm = wid & 1;
    int wn = wid >> 1;
    int mbase = wm * 64;
    int nbase = wn * 32;

    // Global load assignment: (row tid>>2, unit tid&3) and (+64 rows).
    int r0l = tid >> 2, u0l = tid & 3;
    int r1l = r0l + 64;

    int er0 = n0 + r0l, er1 = n0 + r1l;
    int vz0 = (er0 < Nv) ? 16 : 0, vz1 = (er1 < Nv) ? 16 : 0;
    const __nv_bfloat16* gB0 = g_Eb + (size_t)(vz0 ? er0 : 0) * Cv;
    const __nv_bfloat16* gB1 = g_Eb + (size_t)(vz1 ? er1 : 0) * Cv;
    const __nv_bfloat16* gA0 = g_Xb + (size_t)(m0 + r0l) * Cv;
    const __nv_bfloat16* gA1 = g_Xb + (size_t)(m0 + r1l) * Cv;

    float acc[4][4][4];
#pragma unroll
    for (int i = 0; i < 4; i++)
#pragma unroll
        for (int j = 0; j < 4; j++)
#pragma unroll
            for (int q = 0; q < 4; q++) acc[i][j][q] = 0.f;

    auto load_chunk = [&](int c, int p) {
        int koff = c * TK + u0l * 8;
        uint32_t ab = sbase + p * 16384;
        uint32_t bb = ab + 8192;
        cpa16(sw_addr(ab, r0l, u0l), gA0 + koff, 16);
        cpa16(sw_addr(ab, r1l, u0l), gA1 + koff, 16);
        cpa16(sw_addr(bb, r0l, u0l), gB0 + koff, vz0);
        cpa16(sw_addr(bb, r1l, u0l), gB1 + koff, vz1);
        asm volatile("cp.async.commit_group;" ::: "memory");
    };

    load_chunk(0, 0);
    load_chunk(1, 1);

    int buf = 0;
    for (int c = 0; c < KCHUNKS; c++) {
        if (c + 1 < KCHUNKS)
            asm volatile("cp.async.wait_group 1;" ::: "memory");
        else
            asm volatile("cp.async.wait_group 0;" ::: "memory");
        __syncthreads();   // single barrier per chunk (3-stage makes it safe)

        uint32_t bufA = sbase + buf * 16384;
        uint32_t bufB = bufA + 8192;

#pragma unroll
        for (int s = 0; s < 2; s++) {
            int u0 = 2 * s;
            uint32_t aF[4][4];
            uint32_t bF[4][2];
#pragma unroll
            for (int mi = 0; mi < 4; mi++) {
                int r = mbase + mi * 16 + (lane & 15);
                int u = u0 + (lane >> 4);
                uint32_t addr = sw_addr(bufA, r, u);
                asm volatile("ldmatrix.sync.aligned.m8n8.x4.shared.b16 {%0,%1,%2,%3}, [%4];"
                             : "=r"(aF[mi][0]), "=r"(aF[mi][1]), "=r"(aF[mi][2]), "=r"(aF[mi][3])
                             : "r"(addr));
            }
#pragma unroll
            for (int q = 0; q < 2; q++) {
                int r = nbase + q * 16 + ((lane >> 4) << 3) + (lane & 7);
                int u = u0 + ((lane >> 3) & 1);
                uint32_t addr = sw_addr(bufB, r, u);
                uint32_t f0, f1, f2, f3;
                asm volatile("ldmatrix.sync.aligned.m8n8.x4.shared.b16 {%0,%1,%2,%3}, [%4];"
                             : "=r"(f0), "=r"(f1), "=r"(f2), "=r"(f3)
                             : "r"(addr));
                bF[q * 2 + 0][0] = f0; bF[q * 2 + 0][1] = f1;
                bF[q * 2 + 1][0] = f2; bF[q * 2 + 1][1] = f3;
            }
#pragma unroll
            for (int mi = 0; mi < 4; mi++)
#pragma unroll
                for (int nj = 0; nj < 4; nj++) {
                    asm volatile(
                        "mma.sync.aligned.m16n8k16.row.col.f32.bf16.bf16.f32 "
                        "{%0,%1,%2,%3}, {%4,%5,%6,%7}, {%8,%9}, {%0,%1,%2,%3};"
                        : "+f"(acc[mi][nj][0]), "+f"(acc[mi][nj][1]),
                          "+f"(acc[mi][nj][2]), "+f"(acc[mi][nj][3])
                        : "r"(aF[mi][0]), "r"(aF[mi][1]), "r"(aF[mi][2]), "r"(aF[mi][3]),
                          "r"(bF[nj][0]), "r"(bF[nj][1]));
                }
        }

        if (c + 2 < KCHUNKS) load_chunk(c + 2, (c + 2) % STAGES);
        buf = (buf + 1 == STAGES) ? 0 : buf + 1;
    }

    // Epilogue: scale by 1/||e||, convert to bf16 pair, store as uint32
    int gid = lane >> 2;
    int cpair = (lane & 3) * 2;
#pragma unroll
    for (int nj = 0; nj < 4; nj++) {
        int n = n0 + nbase + nj * 8 + cpair;
        if (n >= Nv) continue;    // pair all-or-nothing (Nv even, n even)
        float ri0 = g_rinv[n], ri1 = g_rinv[n + 1];
#pragma unroll
        for (int mi = 0; mi < 4; mi++) {
            int m = m0 + mbase + mi * 16 + gid;
            __nv_bfloat162 h0 = __float22bfloat162_rn(
                make_float2(acc[mi][nj][0] * ri0, acc[mi][nj][1] * ri1));
            __nv_bfloat162 h1 = __float22bfloat162_rn(
                make_float2(acc[mi][nj][2] * ri0, acc[mi][nj][3] * ri1));
            *(uint32_t*)(g_simh + (size_t)m * Nv + n) = *(uint32_t*)&h0;
            *(uint32_t*)(g_simh + (size_t)(m + 8) * Nv + n) = *(uint32_t*)&h1;
        }
    }
}

// ---------------------------------------------------------------------------
// Pass 2: per-row candidate selection, TWO passes over the row:
// 12-bit-prefix histogram (4096 bins) -> threshold bin -> collect.
// One CTA per row; uint4 reads (8 bf16 each).
// ---------------------------------------------------------------------------
__device__ __forceinline__ uint32_t fkey16(uint32_t h) {  // bf16 bits (low 16)
    return (h & 0x8000u) ? ((~h) & 0xFFFFu) : (h | 0x8000u);
}

__global__ __launch_bounds__(256) void select_cand_kernel() {
    int b = blockIdx.x;
    int tid = threadIdx.x;
    const uint4* row = (const uint4*)(g_simh + (size_t)b * Nv);
    constexpr int NW = Nv / 8;  // 6250 uint4

    __shared__ unsigned hist[4096];
    __shared__ unsigned coarse[256];
    __shared__ uint32_t s_thr;
    __shared__ int s_cnt;

#pragma unroll
    for (int i = 0; i < 16; i++) hist[tid + i * 256] = 0;
    __syncthreads();

    // --- pass 1: histogram of top 12 bits of the 16-bit key ---
    for (int w = tid; w < NW; w += 256) {
        uint4 u = row[w];
        atomicAdd(&hist[fkey16(u.x & 0xFFFFu) >> 4], 1u);
        atomicAdd(&hist[fkey16(u.x >> 16) >> 4], 1u);
        atomicAdd(&hist[fkey16(u.y & 0xFFFFu) >> 4], 1u);
        atomicAdd(&hist[fkey16(u.y >> 16) >> 4], 1u);
        atomicAdd(&hist[fkey16(u.z & 0xFFFFu) >> 4], 1u);
        atomicAdd(&hist[fkey16(u.z >> 16) >> 4], 1u);
        atomicAdd(&hist[fkey16(u.w & 0xFFFFu) >> 4], 1u);
        atomicAdd(&hist[fkey16(u.w >> 16) >> 4], 1u);
    }
    __syncthreads();

    // two-level threshold scan
    {
        unsigned cs = 0;
#pragma unroll
        for (int i = 0; i < 16; i++) cs += hist[tid * 16 + i];
        coarse[tid] = cs;
    }
    __syncthreads();
    if (tid == 0) {
        int run = 0, cb = 0;
        for (int v = 255; v >= 0; v--) {
            run += (int)coarse[v];
            if (run >= TOPC) { cb = v; run -= (int)coarse[v]; break; }
        }
        int fb = cb * 16;  // fallback: whole coarse bin
        for (int f = 15; f >= 0; f--) {
            run += (int)hist[cb * 16 + f];
            if (run >= TOPC) { fb = cb * 16 + f; break; }
        }
        s_thr = (uint32_t)fb << 4;
        s_cnt = 0;
    }
    __syncthreads();
    uint32_t thr = s_thr;

    // --- pass 2: collect candidates with key >= thr ---
    for (int w = tid; w < NW; w += 256) {
        uint4 u = row[w];
        uint32_t h[8] = {u.x & 0xFFFFu, u.x >> 16, u.y & 0xFFFFu, u.y >> 16,
                         u.z & 0xFFFFu, u.z >> 16, u.w & 0xFFFFu, u.w >> 16};
#pragma unroll
        for (int i = 0; i < 8; i++) {
            if (fkey16(h[i]) >= thr) {
                int p = atomicAdd(&s_cnt, 1);
                if (p < CAND_MAX) g_cand[b * CAND_MAX + p] = 8 * w + i;
            }
        }
    }
    __syncthreads();
    if (tid == 0) g_ccnt[b] = (s_cnt < CAND_MAX) ? s_cnt : CAND_MAX;
}

// ---------------------------------------------------------------------------
// Pass 3: fp32 rescore (dot * 1/||e||; x-norm is a positive row constant —
// rank-invariant) + exact top-16. One CTA (8 warps) per row.
// ---------------------------------------------------------------------------
__global__ __launch_bounds__(256) void rescore_topk_kernel(const float* __restrict__ X,
                                                           const float* __restrict__ E) {
    int b = blockIdx.x;
    int tid = threadIdx.x;
    int warp = tid >> 5, lane = tid & 31;

    __shared__ float xs[Cv];
    __shared__ float s_sc[CAND_MAX];
    __shared__ int s_id[CAND_MAX];
    __shared__ float rv[256];
    __shared__ int rslot[256];

    for (int c = tid; c < Cv; c += 256) xs[c] = X[(size_t)b * Cv + c];
    __syncthreads();

    int cnt = g_ccnt[b];
    const float4* xs4 = (const float4*)xs;
    for (int ci = warp; ci < cnt; ci += 8) {
        int n = g_cand[b * CAND_MAX + ci];
        const float4* er = (const float4*)(E + (size_t)n * Cv);
        float d = 0.f;
#pragma unroll
        for (int j = 0; j < Cv / 128; j++) {
            float4 e = er[lane + j * 32];
            float4 x = xs4[lane + j * 32];
            d = fmaf(x.x, e.x, d); d = fmaf(x.y, e.y, d);
            d = fmaf(x.z, e.z, d); d = fmaf(x.w, e.w, d);
        }
#pragma unroll
        for (int o = 16; o; o >>= 1) d += __shfl_down_sync(0xffffffffu, d, o);
        if (lane == 0) {
            s_sc[ci] = d * g_rinv[n];
            s_id[ci] = n;
        }
    }
    for (int ci = cnt + tid; ci < CAND_MAX; ci += 256) {
        s_sc[ci] = -1e30f;
        s_id[ci] = 0x7fffffff;
    }
    __syncthreads();

    // exact top-16, descending, tie-break smaller index (fold 512 -> 256)
    for (int r = 0; r < Kv; r++) {
        float bv = s_sc[tid];
        int bs = tid;
        {
            float v2 = s_sc[tid + 256];
            if (v2 > bv || (v2 == bv && s_id[tid + 256] < s_id[bs])) { bv = v2; bs = tid + 256; }
        }
        rv[tid] = bv;
        rslot[tid] = bs;
        __syncthreads();
        for (int s = 128; s > 0; s >>= 1) {
            if (tid < s) {
                float v1 = rv[tid], v2 = rv[tid + s];
                int sl1 = rslot[tid], sl2 = rslot[tid + s];
                bool take2 = (v2 > v1) || (v2 == v1 && s_id[sl2] < s_id[sl1]);
                if (take2) { rv[tid] = v2; rslot[tid] = sl2; }
            }
            __syncthreads();
        }
        if (tid == 0) {
            int sl = rslot[0];
            g_topidx[b * Kv + r] = s_id[sl];
            s_sc[sl] = -1e30f;
        }
        __syncthreads();
    }
}

// ---------------------------------------------------------------------------
// Pass 4: gather with torch's reshape/permute interleave.
// ---------------------------------------------------------------------------
__global__ __launch_bounds__(192) void gather_kernel(const float* __restrict__ E,
                                                     float* __restrict__ out) {
    int rowi = blockIdx.x;  // rowi = b*Kv + j
    int b = rowi >> 4;
    int j = rowi & 15;
    int src = g_topidx[((j << 7) + (b >> 4)) * Kv + (b & 15)];
    const float4* e4 = (const float4*)(E + (size_t)src * Cv);
    float4* o4 = (float4*)(out + (size_t)rowi * Cv);
    o4[threadIdx.x] = e4[threadIdx.x];
}

// ---------------------------------------------------------------------------
extern "C" void kernel_launch(void* const* d_in, const int* in_sizes, int n_in,
                              void* d_out, int out_size) {
    const float* X = (const float*)d_in[0];  // (B, C)
    const float* E = (const float*)d_in[1];  // (N, C)
    float* out = (float*)d_out;              // (B, k, C)

    {
        int n4x = Bv * Cv / 4;
        convert_x_kernel<<<(n4x + 255) / 256, 256>>>(X);
        int blocks = (Nv * 32 + 255) / 256;
        convert_e_norms_kernel<<<blocks, 256>>>(E);
    }
    {
        dim3 grid(NTILES_N, Bv / TM);
        mma_sims_kernel<<<grid, 256>>>();
    }
    select_cand_kernel<<<Bv, 256>>>();
    rescore_topk_kernel<<<Bv, 256>>>(X, E);
    gather_kernel<<<Bv * Kv, 192>>>(E, out);
}

// round 10
// speedup vs baseline: 8.8734x; 1.1407x over previous
#include <cuda_runtime.h>
#include <cuda_bf16.h>
#include <math.h>
#include <stdint.h>

// Problem constants
constexpr int Bv = 2048;   // queries
constexpr int Nv = 50000;  // embeddings
constexpr int Cv = 768;    // channels
constexpr int Kv = 16;     // top-k
constexpr int TOPC = 128;      // candidate margin (absorbs bf16 sim error)
constexpr int CAND_MAX = 512;  // bin-granular threshold => extra candidates

// GEMM tiling
constexpr int TM = 128, TN = 128, TK = 64;
constexpr int NTILES_N = (Nv + TN - 1) / TN;  // 391
constexpr int KCHUNKS = Cv / TK;              // 12
constexpr int STAGES = 3;
constexpr int STAGE_BYTES = 32768;            // A 16KB + B 16KB
constexpr int SMEM_DYN = STAGES * STAGE_BYTES;  // 96 KB

// Scratch (static __device__ — referenced ONLY from device code; passing a
// __device__ global as a host-side kernel arg is UB — the round-2..5 bug).
__device__ __nv_bfloat16  g_simh[(size_t)Bv * Nv];   // ~205 MB bf16 sims
__device__ __nv_bfloat16  g_Xb[(size_t)Bv * Cv];
__device__ __nv_bfloat16  g_Eb[(size_t)Nv * Cv];
__device__ float          g_rinv[NTILES_N * TN];     // 1/||e_n||, padded
__device__ int            g_cand[Bv * CAND_MAX];
__device__ int            g_ccnt[Bv];
__device__ uint32_t       g_thr[Bv];                 // select's 12-bit threshold<<4
__device__ int            g_topidx[Bv * Kv];

// ---------------------------------------------------------------------------
// X: fp32 -> bf16 convert
// ---------------------------------------------------------------------------
__device__ __forceinline__ uint2 cvt4(const float4 v) {
    __nv_bfloat162 p0 = __float22bfloat162_rn(make_float2(v.x, v.y));
    __nv_bfloat162 p1 = __float22bfloat162_rn(make_float2(v.z, v.w));
    uint2 u;
    u.x = *(uint32_t*)&p0;
    u.y = *(uint32_t*)&p1;
    return u;
}

__global__ void convert_x_kernel(const float* __restrict__ src) {
    int i = blockIdx.x * blockDim.x + threadIdx.x;
    if (i >= Bv * Cv / 4) return;
    ((uint2*)g_Xb)[i] = cvt4(((const float4*)src)[i]);
}

// ---------------------------------------------------------------------------
// E: fused fp32->bf16 convert + reciprocal norm. One warp per row.
// ---------------------------------------------------------------------------
__global__ void convert_e_norms_kernel(const float* __restrict__ E) {
    int gw = (blockIdx.x * blockDim.x + threadIdx.x) >> 5;
    int lane = threadIdx.x & 31;
    if (gw >= Nv) return;
    const float4* r = (const float4*)(E + (size_t)gw * Cv);
    uint2* drow = (uint2*)(g_Eb + (size_t)gw * Cv);
    float s = 0.f;
#pragma unroll
    for (int t = 0; t < Cv / 128; t++) {
        float4 v = r[lane + t * 32];
        drow[lane + t * 32] = cvt4(v);
        s = fmaf(v.x, v.x, s); s = fmaf(v.y, v.y, s);
        s = fmaf(v.z, v.z, s); s = fmaf(v.w, v.w, s);
    }
#pragma unroll
    for (int o = 16; o; o >>= 1) s += __shfl_down_sync(0xffffffffu, s, o);
    if (lane == 0) g_rinv[gw] = rsqrtf(s);
}

// ---------------------------------------------------------------------------
// Pass 1: bf16 HMMA GEMM -> bf16 scaled sims (dot * 1/||e||).
// CTA tile 128x128, TK=64 chunks, 3-stage cp.async (96KB dynamic smem),
// ONE syncthreads per chunk. 8 warps (2x4), warp tile 64x32, m16n8k16.
// ---------------------------------------------------------------------------
__device__ __forceinline__ uint32_t smem_u32(const void* p) {
    uint32_t a;
    asm("{ .reg .u64 t; cvta.to.shared.u64 t, %1; cvt.u32.u64 %0, t; }" : "=r"(a) : "l"(p));
    return a;
}

// SMEM addr of (row r, 16B-unit u) in a 128x64 bf16 chunk (128B rows), SW128.
__device__ __forceinline__ uint32_t sw_addr(uint32_t base, int r, int u) {
    return base + (uint32_t)r * 128 + (uint32_t)((u ^ (r & 7)) << 4);
}

__device__ __forceinline__ void cpa16(uint32_t dst, const void* src, int sz) {
    asm volatile("cp.async.cg.shared.global [%0], [%1], 16, %2;"
                 :: "r"(dst), "l"(src), "r"(sz) : "memory");
}

__global__ __launch_bounds__(256) void mma_sims_kernel() {
    extern __shared__ __align__(16) char smem[];
    uint32_t sbase = smem_u32(smem);

    int tid = threadIdx.x;
    int lane = tid & 31, wid = tid >> 5;
    int n0 = blockIdx.x * TN;
    int m0 = blockIdx.y * TM;

    int wm = wid & 1;
    int wn = wid >> 1;
    int mbase = wm * 64;
    int nbase = wn * 32;

    // Global load assignment: unit (row rr+32j, 16B-unit uu), j=0..3, per matrix.
    int rr = tid >> 3, uu = tid & 7;

    const __nv_bfloat16* gA[4];
    const __nv_bfloat16* gB[4];
    int vz[4];
#pragma unroll
    for (int j = 0; j < 4; j++) {
        int r = rr + 32 * j;
        gA[j] = g_Xb + (size_t)(m0 + r) * Cv + uu * 8;
        int er = n0 + r;
        vz[j] = (er < Nv) ? 16 : 0;
        gB[j] = g_Eb + (size_t)(vz[j] ? er : 0) * Cv + uu * 8;
    }

    float acc[4][4][4];
#pragma unroll
    for (int i = 0; i < 4; i++)
#pragma unroll
        for (int j = 0; j < 4; j++)
#pragma unroll
            for (int q = 0; q < 4; q++) acc[i][j][q] = 0.f;

    auto load_chunk = [&](int c, int p) {
        int koff = c * TK;
        uint32_t ab = sbase + p * STAGE_BYTES;
        uint32_t bb = ab + 16384;
#pragma unroll
        for (int j = 0; j < 4; j++) {
            int r = rr + 32 * j;
            cpa16(sw_addr(ab, r, uu), gA[j] + koff, 16);
            cpa16(sw_addr(bb, r, uu), gB[j] + koff, vz[j]);
        }
        asm volatile("cp.async.commit_group;" ::: "memory");
    };

    load_chunk(0, 0);
    load_chunk(1, 1);

    int buf = 0;
    for (int c = 0; c < KCHUNKS; c++) {
        if (c + 1 < KCHUNKS)
            asm volatile("cp.async.wait_group 1;" ::: "memory");
        else
            asm volatile("cp.async.wait_group 0;" ::: "memory");
        __syncthreads();   // single barrier per chunk (3-stage makes it safe)

        uint32_t bufA = sbase + buf * STAGE_BYTES;
        uint32_t bufB = bufA + 16384;

#pragma unroll
        for (int s = 0; s < 4; s++) {   // 4 k-steps of 16 per chunk
            int u0 = 2 * s;
            uint32_t aF[4][4];
            uint32_t bF[4][2];
#pragma unroll
            for (int mi = 0; mi < 4; mi++) {
                int r = mbase + mi * 16 + (lane & 15);
                int u = u0 + (lane >> 4);
                uint32_t addr = sw_addr(bufA, r, u);
                asm volatile("ldmatrix.sync.aligned.m8n8.x4.shared.b16 {%0,%1,%2,%3}, [%4];"
                             : "=r"(aF[mi][0]), "=r"(aF[mi][1]), "=r"(aF[mi][2]), "=r"(aF[mi][3])
                             : "r"(addr));
            }
#pragma unroll
            for (int q = 0; q < 2; q++) {
                int r = nbase + q * 16 + ((lane >> 4) << 3) + (lane & 7);
                int u = u0 + ((lane >> 3) & 1);
                uint32_t addr = sw_addr(bufB, r, u);
                uint32_t f0, f1, f2, f3;
                asm volatile("ldmatrix.sync.aligned.m8n8.x4.shared.b16 {%0,%1,%2,%3}, [%4];"
                             : "=r"(f0), "=r"(f1), "=r"(f2), "=r"(f3)
                             : "r"(addr));
                bF[q * 2 + 0][0] = f0; bF[q * 2 + 0][1] = f1;
                bF[q * 2 + 1][0] = f2; bF[q * 2 + 1][1] = f3;
            }
#pragma unroll
            for (int mi = 0; mi < 4; mi++)
#pragma unroll
                for (int nj = 0; nj < 4; nj++) {
                    asm volatile(
                        "mma.sync.aligned.m16n8k16.row.col.f32.bf16.bf16.f32 "
                        "{%0,%1,%2,%3}, {%4,%5,%6,%7}, {%8,%9}, {%0,%1,%2,%3};"
                        : "+f"(acc[mi][nj][0]), "+f"(acc[mi][nj][1]),
                          "+f"(acc[mi][nj][2]), "+f"(acc[mi][nj][3])
                        : "r"(aF[mi][0]), "r"(aF[mi][1]), "r"(aF[mi][2]), "r"(aF[mi][3]),
                          "r"(bF[nj][0]), "r"(bF[nj][1]));
                }
        }

        if (c + 2 < KCHUNKS) load_chunk(c + 2, (c + 2) % STAGES);
        buf = (buf + 1 == STAGES) ? 0 : buf + 1;
    }

    // Epilogue: scale by 1/||e||, convert to bf16 pair, store as uint32
    int gid = lane >> 2;
    int cpair = (lane & 3) * 2;
#pragma unroll
    for (int nj = 0; nj < 4; nj++) {
        int n = n0 + nbase + nj * 8 + cpair;
        if (n >= Nv) continue;    // pair all-or-nothing (Nv even, n even)
        float ri0 = g_rinv[n], ri1 = g_rinv[n + 1];
#pragma unroll
        for (int mi = 0; mi < 4; mi++) {
            int m = m0 + mbase + mi * 16 + gid;
            __nv_bfloat162 h0 = __float22bfloat162_rn(
                make_float2(acc[mi][nj][0] * ri0, acc[mi][nj][1] * ri1));
            __nv_bfloat162 h1 = __float22bfloat162_rn(
                make_float2(acc[mi][nj][2] * ri0, acc[mi][nj][3] * ri1));
            *(uint32_t*)(g_simh + (size_t)m * Nv + n) = *(uint32_t*)&h0;
            *(uint32_t*)(g_simh + (size_t)(m + 8) * Nv + n) = *(uint32_t*)&h1;
        }
    }
}

// ---------------------------------------------------------------------------
// Pass 2: per-row candidate selection, TWO passes over the row:
// 12-bit-prefix histogram (4096 bins) -> threshold bin -> collect.
// One CTA per row; uint4 reads (8 bf16 each). Stores threshold for rescore.
// ---------------------------------------------------------------------------
__device__ __forceinline__ uint32_t fkey16(uint32_t h) {  // bf16 bits (low 16)
    return (h & 0x8000u) ? ((~h) & 0xFFFFu) : (h | 0x8000u);
}

__global__ __launch_bounds__(256) void select_cand_kernel() {
    int b = blockIdx.x;
    int tid = threadIdx.x;
    const uint4* row = (const uint4*)(g_simh + (size_t)b * Nv);
    constexpr int NW = Nv / 8;  // 6250 uint4

    __shared__ unsigned hist[4096];
    __shared__ unsigned coarse[256];
    __shared__ uint32_t s_thr;
    __shared__ int s_cnt;

#pragma unroll
    for (int i = 0; i < 16; i++) hist[tid + i * 256] = 0;
    __syncthreads();

    // --- pass 1: histogram of top 12 bits of the 16-bit key ---
    for (int w = tid; w < NW; w += 256) {
        uint4 u = row[w];
        atomicAdd(&hist[fkey16(u.x & 0xFFFFu) >> 4], 1u);
        atomicAdd(&hist[fkey16(u.x >> 16) >> 4], 1u);
        atomicAdd(&hist[fkey16(u.y & 0xFFFFu) >> 4], 1u);
        atomicAdd(&hist[fkey16(u.y >> 16) >> 4], 1u);
        atomicAdd(&hist[fkey16(u.z & 0xFFFFu) >> 4], 1u);
        atomicAdd(&hist[fkey16(u.z >> 16) >> 4], 1u);
        atomicAdd(&hist[fkey16(u.w & 0xFFFFu) >> 4], 1u);
        atomicAdd(&hist[fkey16(u.w >> 16) >> 4], 1u);
    }
    __syncthreads();

    // two-level threshold scan
    {
        unsigned cs = 0;
#pragma unroll
        for (int i = 0; i < 16; i++) cs += hist[tid * 16 + i];
        coarse[tid] = cs;
    }
    __syncthreads();
    if (tid == 0) {
        int run = 0, cb = 0;
        for (int v = 255; v >= 0; v--) {
            run += (int)coarse[v];
            if (run >= TOPC) { cb = v; run -= (int)coarse[v]; break; }
        }
        int fb = cb * 16;  // fallback: whole coarse bin
        for (int f = 15; f >= 0; f--) {
            run += (int)hist[cb * 16 + f];
            if (run >= TOPC) { fb = cb * 16 + f; break; }
        }
        s_thr = (uint32_t)fb << 4;
        g_thr[b] = s_thr;
        s_cnt = 0;
    }
    __syncthreads();
    uint32_t thr = s_thr;

    // --- pass 2: collect candidates with key >= thr ---
    for (int w = tid; w < NW; w += 256) {
        uint4 u = row[w];
        uint32_t h[8] = {u.x & 0xFFFFu, u.x >> 16, u.y & 0xFFFFu, u.y >> 16,
                         u.z & 0xFFFFu, u.z >> 16, u.w & 0xFFFFu, u.w >> 16};
#pragma unroll
        for (int i = 0; i < 8; i++) {
            if (fkey16(h[i]) >= thr) {
                int p = atomicAdd(&s_cnt, 1);
                if (p < CAND_MAX) g_cand[b * CAND_MAX + p] = 8 * w + i;
            }
        }
    }
    __syncthreads();
    if (tid == 0) g_ccnt[b] = (s_cnt < CAND_MAX) ? s_cnt : CAND_MAX;
}

// ---------------------------------------------------------------------------
// Pass 3: exact-key pruning to top-TOPC, then fp32 rescore (dot * 1/||e||;
// x-norm is a positive row constant — rank-invariant) + exact top-16.
// One CTA (8 warps) per row, warp per candidate.
// ---------------------------------------------------------------------------
__global__ __launch_bounds__(256) void rescore_topk_kernel(const float* __restrict__ X,
                                                           const float* __restrict__ E) {
    int b = blockIdx.x;
    int tid = threadIdx.x;
    int warp = tid >> 5, lane = tid & 31;

    __shared__ float xs[Cv];
    __shared__ float s_sc[CAND_MAX];
    __shared__ int s_id[CAND_MAX];
    __shared__ uint16_t s_key[CAND_MAX];
    __shared__ int s_hist[17];
    __shared__ uint32_t s_thr2;
    __shared__ float rv[256];
    __shared__ int rslot[256];

    for (int c = tid; c < Cv; c += 256) xs[c] = X[(size_t)b * Cv + c];
    if (tid < 17) s_hist[tid] = 0;
    for (int ci = tid; ci < CAND_MAX; ci += 256) {
        s_sc[ci] = -1e30f;
        s_id[ci] = 0x7fffffff;
    }
    __syncthreads();

    int cnt = g_ccnt[b];
    uint32_t thr = g_thr[b];
    int fb = (int)(thr >> 4);

    // load exact bf16 keys; histogram sub-bins (all keys >= thr by construction)
    for (int ci = tid; ci < cnt; ci += 256) {
        int n = g_cand[b * CAND_MAX + ci];
        uint32_t hb = ((const uint16_t*)g_simh)[(size_t)b * Nv + n];
        uint32_t k = fkey16(hb);
        s_key[ci] = (uint16_t)k;
        if ((int)(k >> 4) > fb) atomicAdd(&s_hist[16], 1);
        else atomicAdd(&s_hist[(int)(k & 15u)], 1);
    }
    __syncthreads();
    if (tid == 0) {
        int run = s_hist[16];
        uint32_t t2 = thr;
        for (int v = 15; v >= 0; v--) {
            run += s_hist[v];
            if (run >= TOPC) { t2 = thr + (uint32_t)v; break; }
        }
        s_thr2 = t2;
    }
    __syncthreads();
    uint32_t thr2 = s_thr2;

    const float4* xs4 = (const float4*)xs;
    for (int ci = warp; ci < cnt; ci += 8) {
        if ((uint32_t)s_key[ci] < thr2) continue;   // pruned (below exact rank-TOPC key)
        int n = g_cand[b * CAND_MAX + ci];
        const float4* er = (const float4*)(E + (size_t)n * Cv);
        float d = 0.f;
#pragma unroll
        for (int j = 0; j < Cv / 128; j++) {
            float4 e = er[lane + j * 32];
            float4 x = xs4[lane + j * 32];
            d = fmaf(x.x, e.x, d); d = fmaf(x.y, e.y, d);
            d = fmaf(x.z, e.z, d); d = fmaf(x.w, e.w, d);
        }
#pragma unroll
        for (int o = 16; o; o >>= 1) d += __shfl_down_sync(0xffffffffu, d, o);
        if (lane == 0) {
            s_sc[ci] = d * g_rinv[n];
            s_id[ci] = n;
        }
    }
    __syncthreads();

    // exact top-16, descending, tie-break smaller index (fold 512 -> 256)
    for (int r = 0; r < Kv; r++) {
        float bv = s_sc[tid];
        int bs = tid;
        {
            float v2 = s_sc[tid + 256];
            if (v2 > bv || (v2 == bv && s_id[tid + 256] < s_id[bs])) { bv = v2; bs = tid + 256; }
        }
        rv[tid] = bv;
        rslot[tid] = bs;
        __syncthreads();
        for (int s = 128; s > 0; s >>= 1) {
            if (tid < s) {
                float v1 = rv[tid], v2 = rv[tid + s];
                int sl1 = rslot[tid], sl2 = rslot[tid + s];
                bool take2 = (v2 > v1) || (v2 == v1 && s_id[sl2] < s_id[sl1]);
                if (take2) { rv[tid] = v2; rslot[tid] = sl2; }
            }
            __syncthreads();
        }
        if (tid == 0) {
            int sl = rslot[0];
            g_topidx[b * Kv + r] = s_id[sl];
            s_sc[sl] = -1e30f;
        }
        __syncthreads();
    }
}

// ---------------------------------------------------------------------------
// Pass 4: gather with torch's reshape/permute interleave.
// ---------------------------------------------------------------------------
__global__ __launch_bounds__(192) void gather_kernel(const float* __restrict__ E,
                                                     float* __restrict__ out) {
    int rowi = blockIdx.x;  // rowi = b*Kv + j
    int b = rowi >> 4;
    int j = rowi & 15;
    int src = g_topidx[((j << 7) + (b >> 4)) * Kv + (b & 15)];
    const float4* e4 = (const float4*)(E + (size_t)src * Cv);
    float4* o4 = (float4*)(out + (size_t)rowi * Cv);
    o4[threadIdx.x] = e4[threadIdx.x];
}

// ---------------------------------------------------------------------------
extern "C" void kernel_launch(void* const* d_in, const int* in_sizes, int n_in,
                              void* d_out, int out_size) {
    const float* X = (const float*)d_in[0];  // (B, C)
    const float* E = (const float*)d_in[1];  // (N, C)
    float* out = (float*)d_out;              // (B, k, C)

    {
        int n4x = Bv * Cv / 4;
        convert_x_kernel<<<(n4x + 255) / 256, 256>>>(X);
        int blocks = (Nv * 32 + 255) / 256;
        convert_e_norms_kernel<<<blocks, 256>>>(E);
    }
    {
        cudaFuncSetAttribute(mma_sims_kernel,
                             cudaFuncAttributeMaxDynamicSharedMemorySize, SMEM_DYN);
        dim3 grid(NTILES_N, Bv / TM);
        mma_sims_kernel<<<grid, 256, SMEM_DYN>>>();
    }
    select_cand_kernel<<<Bv, 256>>>();
    rescore_topk_kernel<<<Bv, 256>>>(X, E);
    gather_kernel<<<Bv * Kv, 192>>>(E, out);
}

// round 11
// speedup vs baseline: 8.8738x; 1.0000x over previous
#include <cuda_runtime.h>
#include <cuda_bf16.h>
#include <math.h>
#include <stdint.h>

// Problem constants
constexpr int Bv = 2048;   // queries
constexpr int Nv = 50000;  // embeddings
constexpr int Cv = 768;    // channels
constexpr int Kv = 16;     // top-k
constexpr int TOPC = 128;      // candidate margin (absorbs bf16 sim error)
constexpr int CAND_MAX = 512;  // bin-granular threshold => extra candidates

// GEMM tiling
constexpr int TM = 128, TN = 128, TK = 64;
constexpr int NTILES_N = (Nv + TN - 1) / TN;  // 391
constexpr int KCHUNKS = Cv / TK;              // 12
constexpr int STAGES = 3;
constexpr int STAGE_BYTES = 32768;            // A 16KB + B 16KB
constexpr int SMEM_DYN = STAGES * STAGE_BYTES;  // 96 KB

// Scratch (static __device__ — referenced ONLY from device code; passing a
// __device__ global as a host-side kernel arg is UB — the round-2..5 bug).
__device__ __nv_bfloat16  g_simh[(size_t)Bv * Nv];   // ~205 MB bf16 sims
__device__ __nv_bfloat16  g_Xb[(size_t)Bv * Cv];
__device__ __nv_bfloat16  g_Eb[(size_t)Nv * Cv];
__device__ float          g_rinv[NTILES_N * TN];     // 1/||e_n||, padded
__device__ int            g_cand[Bv * CAND_MAX];
__device__ int            g_ccnt[Bv];
__device__ uint32_t       g_thr[Bv];                 // select's 12-bit threshold<<4
__device__ int            g_topidx[Bv * Kv];

// ---------------------------------------------------------------------------
// X: fp32 -> bf16 convert
// ---------------------------------------------------------------------------
__device__ __forceinline__ uint2 cvt4(const float4 v) {
    __nv_bfloat162 p0 = __float22bfloat162_rn(make_float2(v.x, v.y));
    __nv_bfloat162 p1 = __float22bfloat162_rn(make_float2(v.z, v.w));
    uint2 u;
    u.x = *(uint32_t*)&p0;
    u.y = *(uint32_t*)&p1;
    return u;
}

__global__ void convert_x_kernel(const float* __restrict__ src) {
    int i = blockIdx.x * blockDim.x + threadIdx.x;
    if (i >= Bv * Cv / 4) return;
    ((uint2*)g_Xb)[i] = cvt4(((const float4*)src)[i]);
}

// ---------------------------------------------------------------------------
// E: fused fp32->bf16 convert + reciprocal norm. One warp per row.
// ---------------------------------------------------------------------------
__global__ void convert_e_norms_kernel(const float* __restrict__ E) {
    int gw = (blockIdx.x * blockDim.x + threadIdx.x) >> 5;
    int lane = threadIdx.x & 31;
    if (gw >= Nv) return;
    const float4* r = (const float4*)(E + (size_t)gw * Cv);
    uint2* drow = (uint2*)(g_Eb + (size_t)gw * Cv);
    float s = 0.f;
#pragma unroll
    for (int t = 0; t < Cv / 128; t++) {
        float4 v = r[lane + t * 32];
        drow[lane + t * 32] = cvt4(v);
        s = fmaf(v.x, v.x, s); s = fmaf(v.y, v.y, s);
        s = fmaf(v.z, v.z, s); s = fmaf(v.w, v.w, s);
    }
#pragma unroll
    for (int o = 16; o; o >>= 1) s += __shfl_down_sync(0xffffffffu, s, o);
    if (lane == 0) g_rinv[gw] = rsqrtf(s);
}

// ---------------------------------------------------------------------------
// Pass 1: bf16 HMMA GEMM -> bf16 scaled sims (dot * 1/||e||).
// CTA tile 128x128, TK=64 chunks, 3-stage cp.async (96KB dynamic smem),
// ONE syncthreads per chunk. 8 warps (2x4), warp tile 64x32, m16n8k16.
// ---------------------------------------------------------------------------
__device__ __forceinline__ uint32_t smem_u32(const void* p) {
    uint32_t a;
    asm("{ .reg .u64 t; cvta.to.shared.u64 t, %1; cvt.u32.u64 %0, t; }" : "=r"(a) : "l"(p));
    return a;
}

// SMEM addr of (row r, 16B-unit u) in a 128x64 bf16 chunk (128B rows), SW128.
__device__ __forceinline__ uint32_t sw_addr(uint32_t base, int r, int u) {
    return base + (uint32_t)r * 128 + (uint32_t)((u ^ (r & 7)) << 4);
}

__device__ __forceinline__ void cpa16(uint32_t dst, const void* src, int sz) {
    asm volatile("cp.async.cg.shared.global [%0], [%1], 16, %2;"
                 :: "r"(dst), "l"(src), "r"(sz) : "memory");
}

__global__ __launch_bounds__(256) void mma_sims_kernel() {
    extern __shared__ __align__(16) char smem[];
    uint32_t sbase = smem_u32(smem);

    int tid = threadIdx.x;
    int lane = tid & 31, wid = tid >> 5;
    int n0 = blockIdx.x * TN;
    int m0 = blockIdx.y * TM;

    int wm = wid & 1;
    int wn = wid >> 1;
    int mbase = wm * 64;
    int nbase = wn * 32;

    // Global load assignment: unit (row rr+32j, 16B-unit uu), j=0..3, per matrix.
    int rr = tid >> 3, uu = tid & 7;

    const __nv_bfloat16* gA[4];
    const __nv_bfloat16* gB[4];
    int vz[4];
#pragma unroll
    for (int j = 0; j < 4; j++) {
        int r = rr + 32 * j;
        gA[j] = g_Xb + (size_t)(m0 + r) * Cv + uu * 8;
        int er = n0 + r;
        vz[j] = (er < Nv) ? 16 : 0;
        gB[j] = g_Eb + (size_t)(vz[j] ? er : 0) * Cv + uu * 8;
    }

    float acc[4][4][4];
#pragma unroll
    for (int i = 0; i < 4; i++)
#pragma unroll
        for (int j = 0; j < 4; j++)
#pragma unroll
            for (int q = 0; q < 4; q++) acc[i][j][q] = 0.f;

    auto load_chunk = [&](int c, int p) {
        int koff = c * TK;
        uint32_t ab = sbase + p * STAGE_BYTES;
        uint32_t bb = ab + 16384;
#pragma unroll
        for (int j = 0; j < 4; j++) {
            int r = rr + 32 * j;
            cpa16(sw_addr(ab, r, uu), gA[j] + koff, 16);
            cpa16(sw_addr(bb, r, uu), gB[j] + koff, vz[j]);
        }
        asm volatile("cp.async.commit_group;" ::: "memory");
    };

    load_chunk(0, 0);
    load_chunk(1, 1);

    int buf = 0;
    for (int c = 0; c < KCHUNKS; c++) {
        if (c + 1 < KCHUNKS)
            asm volatile("cp.async.wait_group 1;" ::: "memory");
        else
            asm volatile("cp.async.wait_group 0;" ::: "memory");
        __syncthreads();   // single barrier per chunk (3-stage makes it safe)

        uint32_t bufA = sbase + buf * STAGE_BYTES;
        uint32_t bufB = bufA + 16384;

#pragma unroll
        for (int s = 0; s < 4; s++) {   // 4 k-steps of 16 per chunk
            int u0 = 2 * s;
            uint32_t aF[4][4];
            uint32_t bF[4][2];
#pragma unroll
            for (int mi = 0; mi < 4; mi++) {
                int r = mbase + mi * 16 + (lane & 15);
                int u = u0 + (lane >> 4);
                uint32_t addr = sw_addr(bufA, r, u);
                asm volatile("ldmatrix.sync.aligned.m8n8.x4.shared.b16 {%0,%1,%2,%3}, [%4];"
                             : "=r"(aF[mi][0]), "=r"(aF[mi][1]), "=r"(aF[mi][2]), "=r"(aF[mi][3])
                             : "r"(addr));
            }
#pragma unroll
            for (int q = 0; q < 2; q++) {
                int r = nbase + q * 16 + ((lane >> 4) << 3) + (lane & 7);
                int u = u0 + ((lane >> 3) & 1);
                uint32_t addr = sw_addr(bufB, r, u);
                uint32_t f0, f1, f2, f3;
                asm volatile("ldmatrix.sync.aligned.m8n8.x4.shared.b16 {%0,%1,%2,%3}, [%4];"
                             : "=r"(f0), "=r"(f1), "=r"(f2), "=r"(f3)
                             : "r"(addr));
                bF[q * 2 + 0][0] = f0; bF[q * 2 + 0][1] = f1;
                bF[q * 2 + 1][0] = f2; bF[q * 2 + 1][1] = f3;
            }
#pragma unroll
            for (int mi = 0; mi < 4; mi++)
#pragma unroll
                for (int nj = 0; nj < 4; nj++) {
                    asm volatile(
                        "mma.sync.aligned.m16n8k16.row.col.f32.bf16.bf16.f32 "
                        "{%0,%1,%2,%3}, {%4,%5,%6,%7}, {%8,%9}, {%0,%1,%2,%3};"
                        : "+f"(acc[mi][nj][0]), "+f"(acc[mi][nj][1]),
                          "+f"(acc[mi][nj][2]), "+f"(acc[mi][nj][3])
                        : "r"(aF[mi][0]), "r"(aF[mi][1]), "r"(aF[mi][2]), "r"(aF[mi][3]),
                          "r"(bF[nj][0]), "r"(bF[nj][1]));
                }
        }

        if (c + 2 < KCHUNKS) load_chunk(c + 2, (c + 2) % STAGES);
        buf = (buf + 1 == STAGES) ? 0 : buf + 1;
    }

    // Epilogue: scale by 1/||e||, convert to bf16 pair, store as uint32
    int gid = lane >> 2;
    int cpair = (lane & 3) * 2;
#pragma unroll
    for (int nj = 0; nj < 4; nj++) {
        int n = n0 + nbase + nj * 8 + cpair;
        if (n >= Nv) continue;    // pair all-or-nothing (Nv even, n even)
        float ri0 = g_rinv[n], ri1 = g_rinv[n + 1];
#pragma unroll
        for (int mi = 0; mi < 4; mi++) {
            int m = m0 + mbase + mi * 16 + gid;
            __nv_bfloat162 h0 = __float22bfloat162_rn(
                make_float2(acc[mi][nj][0] * ri0, acc[mi][nj][1] * ri1));
            __nv_bfloat162 h1 = __float22bfloat162_rn(
                make_float2(acc[mi][nj][2] * ri0, acc[mi][nj][3] * ri1));
            *(uint32_t*)(g_simh + (size_t)m * Nv + n) = *(uint32_t*)&h0;
            *(uint32_t*)(g_simh + (size_t)(m + 8) * Nv + n) = *(uint32_t*)&h1;
        }
    }
}

// ---------------------------------------------------------------------------
// Pass 2: per-row candidate selection, TWO passes over the row:
// 12-bit-prefix histogram (4096 bins) -> threshold bin -> collect.
// One CTA per row; uint4 reads (8 bf16 each). Stores threshold for rescore.
// ---------------------------------------------------------------------------
__device__ __forceinline__ uint32_t fkey16(uint32_t h) {  // bf16 bits (low 16)
    return (h & 0x8000u) ? ((~h) & 0xFFFFu) : (h | 0x8000u);
}

__global__ __launch_bounds__(256) void select_cand_kernel() {
    int b = blockIdx.x;
    int tid = threadIdx.x;
    const uint4* row = (const uint4*)(g_simh + (size_t)b * Nv);
    constexpr int NW = Nv / 8;  // 6250 uint4

    __shared__ unsigned hist[4096];
    __shared__ unsigned coarse[256];
    __shared__ uint32_t s_thr;
    __shared__ int s_cnt;

#pragma unroll
    for (int i = 0; i < 16; i++) hist[tid + i * 256] = 0;
    __syncthreads();

    // --- pass 1: histogram of top 12 bits of the 16-bit key ---
    for (int w = tid; w < NW; w += 256) {
        uint4 u = row[w];
        atomicAdd(&hist[fkey16(u.x & 0xFFFFu) >> 4], 1u);
        atomicAdd(&hist[fkey16(u.x >> 16) >> 4], 1u);
        atomicAdd(&hist[fkey16(u.y & 0xFFFFu) >> 4], 1u);
        atomicAdd(&hist[fkey16(u.y >> 16) >> 4], 1u);
        atomicAdd(&hist[fkey16(u.z & 0xFFFFu) >> 4], 1u);
        atomicAdd(&hist[fkey16(u.z >> 16) >> 4], 1u);
        atomicAdd(&hist[fkey16(u.w & 0xFFFFu) >> 4], 1u);
        atomicAdd(&hist[fkey16(u.w >> 16) >> 4], 1u);
    }
    __syncthreads();

    // two-level threshold scan
    {
        unsigned cs = 0;
#pragma unroll
        for (int i = 0; i < 16; i++) cs += hist[tid * 16 + i];
        coarse[tid] = cs;
    }
    __syncthreads();
    if (tid == 0) {
        int run = 0, cb = 0;
        for (int v = 255; v >= 0; v--) {
            run += (int)coarse[v];
            if (run >= TOPC) { cb = v; run -= (int)coarse[v]; break; }
        }
        int fb = cb * 16;  // fallback: whole coarse bin
        for (int f = 15; f >= 0; f--) {
            run += (int)hist[cb * 16 + f];
            if (run >= TOPC) { fb = cb * 16 + f; break; }
        }
        s_thr = (uint32_t)fb << 4;
        g_thr[b] = s_thr;
        s_cnt = 0;
    }
    __syncthreads();
    uint32_t thr = s_thr;

    // --- pass 2: collect candidates with key >= thr ---
    for (int w = tid; w < NW; w += 256) {
        uint4 u = row[w];
        uint32_t h[8] = {u.x & 0xFFFFu, u.x >> 16, u.y & 0xFFFFu, u.y >> 16,
                         u.z & 0xFFFFu, u.z >> 16, u.w & 0xFFFFu, u.w >> 16};
#pragma unroll
        for (int i = 0; i < 8; i++) {
            if (fkey16(h[i]) >= thr) {
                int p = atomicAdd(&s_cnt, 1);
                if (p < CAND_MAX) g_cand[b * CAND_MAX + p] = 8 * w + i;
            }
        }
    }
    __syncthreads();
    if (tid == 0) g_ccnt[b] = (s_cnt < CAND_MAX) ? s_cnt : CAND_MAX;
}

// ---------------------------------------------------------------------------
// Pass 3: exact-key pruning to top-TOPC, then fp32 rescore (dot * 1/||e||;
// x-norm is a positive row constant — rank-invariant) + exact top-16.
// One CTA (8 warps) per row, warp per candidate.
// ---------------------------------------------------------------------------
__global__ __launch_bounds__(256) void rescore_topk_kernel(const float* __restrict__ X,
                                                           const float* __restrict__ E) {
    int b = blockIdx.x;
    int tid = threadIdx.x;
    int warp = tid >> 5, lane = tid & 31;

    __shared__ float xs[Cv];
    __shared__ float s_sc[CAND_MAX];
    __shared__ int s_id[CAND_MAX];
    __shared__ uint16_t s_key[CAND_MAX];
    __shared__ int s_hist[17];
    __shared__ uint32_t s_thr2;
    __shared__ float rv[256];
    __shared__ int rslot[256];

    for (int c = tid; c < Cv; c += 256) xs[c] = X[(size_t)b * Cv + c];
    if (tid < 17) s_hist[tid] = 0;
    for (int ci = tid; ci < CAND_MAX; ci += 256) {
        s_sc[ci] = -1e30f;
        s_id[ci] = 0x7fffffff;
    }
    __syncthreads();

    int cnt = g_ccnt[b];
    uint32_t thr = g_thr[b];
    int fb = (int)(thr >> 4);

    // load exact bf16 keys; histogram sub-bins (all keys >= thr by construction)
    for (int ci = tid; ci < cnt; ci += 256) {
        int n = g_cand[b * CAND_MAX + ci];
        uint32_t hb = ((const uint16_t*)g_simh)[(size_t)b * Nv + n];
        uint32_t k = fkey16(hb);
        s_key[ci] = (uint16_t)k;
        if ((int)(k >> 4) > fb) atomicAdd(&s_hist[16], 1);
        else atomicAdd(&s_hist[(int)(k & 15u)], 1);
    }
    __syncthreads();
    if (tid == 0) {
        int run = s_hist[16];
        uint32_t t2 = thr;
        for (int v = 15; v >= 0; v--) {
            run += s_hist[v];
            if (run >= TOPC) { t2 = thr + (uint32_t)v; break; }
        }
        s_thr2 = t2;
    }
    __syncthreads();
    uint32_t thr2 = s_thr2;

    const float4* xs4 = (const float4*)xs;
    for (int ci = warp; ci < cnt; ci += 8) {
        if ((uint32_t)s_key[ci] < thr2) continue;   // pruned (below exact rank-TOPC key)
        int n = g_cand[b * CAND_MAX + ci];
        const float4* er = (const float4*)(E + (size_t)n * Cv);
        float d = 0.f;
#pragma unroll
        for (int j = 0; j < Cv / 128; j++) {
            float4 e = er[lane + j * 32];
            float4 x = xs4[lane + j * 32];
            d = fmaf(x.x, e.x, d); d = fmaf(x.y, e.y, d);
            d = fmaf(x.z, e.z, d); d = fmaf(x.w, e.w, d);
        }
#pragma unroll
        for (int o = 16; o; o >>= 1) d += __shfl_down_sync(0xffffffffu, d, o);
        if (lane == 0) {
            s_sc[ci] = d * g_rinv[n];
            s_id[ci] = n;
        }
    }
    __syncthreads();

    // exact top-16, descending, tie-break smaller index (fold 512 -> 256)
    for (int r = 0; r < Kv; r++) {
        float bv = s_sc[tid];
        int bs = tid;
        {
            float v2 = s_sc[tid + 256];
            if (v2 > bv || (v2 == bv && s_id[tid + 256] < s_id[bs])) { bv = v2; bs = tid + 256; }
        }
        rv[tid] = bv;
        rslot[tid] = bs;
        __syncthreads();
        for (int s = 128; s > 0; s >>= 1) {
            if (tid < s) {
                float v1 = rv[tid], v2 = rv[tid + s];
                int sl1 = rslot[tid], sl2 = rslot[tid + s];
                bool take2 = (v2 > v1) || (v2 == v1 && s_id[sl2] < s_id[sl1]);
                if (take2) { rv[tid] = v2; rslot[tid] = sl2; }
            }
            __syncthreads();
        }
        if (tid == 0) {
            int sl = rslot[0];
            g_topidx[b * Kv + r] = s_id[sl];
            s_sc[sl] = -1e30f;
        }
        __syncthreads();
    }
}

// ---------------------------------------------------------------------------
// Pass 4: gather with torch's reshape/permute interleave.
// ---------------------------------------------------------------------------
__global__ __launch_bounds__(192) void gather_kernel(const float* __restrict__ E,
                                                     float* __restrict__ out) {
    int rowi = blockIdx.x;  // rowi = b*Kv + j
    int b = rowi >> 4;
    int j = rowi & 15;
    int src = g_topidx[((j << 7) + (b >> 4)) * Kv + (b & 15)];
    const float4* e4 = (const float4*)(E + (size_t)src * Cv);
    float4* o4 = (float4*)(out + (size_t)rowi * Cv);
    o4[threadIdx.x] = e4[threadIdx.x];
}

// ---------------------------------------------------------------------------
extern "C" void kernel_launch(void* const* d_in, const int* in_sizes, int n_in,
                              void* d_out, int out_size) {
    const float* X = (const float*)d_in[0];  // (B, C)
    const float* E = (const float*)d_in[1];  // (N, C)
    float* out = (float*)d_out;              // (B, k, C)

    {
        int n4x = Bv * Cv / 4;
        convert_x_kernel<<<(n4x + 255) / 256, 256>>>(X);
        int blocks = (Nv * 32 + 255) / 256;
        convert_e_norms_kernel<<<blocks, 256>>>(E);
    }
    {
        cudaFuncSetAttribute(mma_sims_kernel,
                             cudaFuncAttributeMaxDynamicSharedMemorySize, SMEM_DYN);
        dim3 grid(NTILES_N, Bv / TM);
        mma_sims_kernel<<<grid, 256, SMEM_DYN>>>();
    }
    select_cand_kernel<<<Bv, 256>>>();
    rescore_topk_kernel<<<Bv, 256>>>(X, E);
    gather_kernel<<<Bv * Kv, 192>>>(E, out);
}